// round 13
// baseline (speedup 1.0000x reference)
#include <cuda_runtime.h>
#include <cuda_fp16.h>
#include <math.h>
#include <stdint.h>

#define NN 1024
#define BB 4
#define TT 24
#define FF 96
#define RR (NN*96)       // 98304 rows (== B*T*N)
#define RGRID (RR/128)   // 768

// ---------------- scratch (device globals; no allocs allowed) ----------------
__device__ __half g_h3[3*(size_t)RR*96];  // spatial GAT h (fp16), per gat
__device__ float g_el3[3*RR*3];
__device__ float g_er3[3*RR*3];
__device__ float g_hg[(size_t)RR*96];     // temporal hg (fp32), row = (b*N+n)*24+t
__device__ float g_elg[RR*4];
__device__ float g_erg[RR*4];
__device__ float g_spatial[(size_t)RR*96];
__device__ float g_temporal[(size_t)RR*96];
__device__ float g_attnT[BB*TT*TT];

// ---------------- tf32 helpers ----------------
__device__ __forceinline__ uint32_t f2tf32(float x) {
    uint32_t r; asm("cvt.rna.tf32.f32 %0, %1;" : "=r"(r) : "f"(x)); return r;
}
__device__ __forceinline__ void mma_tf32(float* c, const uint32_t* a, uint32_t b0, uint32_t b1) {
    asm volatile("mma.sync.aligned.m16n8k8.row.col.f32.tf32.tf32.f32 "
        "{%0,%1,%2,%3}, {%4,%5,%6,%7}, {%8,%9}, {%0,%1,%2,%3};"
        : "+f"(c[0]), "+f"(c[1]), "+f"(c[2]), "+f"(c[3])
        : "r"(a[0]), "r"(a[1]), "r"(a[2]), "r"(a[3]), "r"(b0), "r"(b1));
}

// =============== spatial GEMM: 128 rows x 96 cols, ALL 3 GATs per block ======
__global__ __launch_bounds__(256)
void gemm_tc_sp(const float* __restrict__ X, const float* __restrict__ Emb,
                const float* __restrict__ W0, const float* __restrict__ W1, const float* __restrict__ W2,
                const float* __restrict__ al0, const float* __restrict__ al1, const float* __restrict__ al2,
                const float* __restrict__ ar0, const float* __restrict__ ar1, const float* __restrict__ ar2)
{
    extern __shared__ float sm[];
    float*    Xs = sm;                                 // [128][100] fp32
    uint32_t* Ws = (uint32_t*)(sm + 128*100);          // 3 x [96][104] tf32

    const int tid = threadIdx.x;
    const int row0 = blockIdx.x * 128;
    const float* Wp[3]  = {W0, W1, W2};
    const float* alp[3] = {al0, al1, al2};
    const float* arp[3] = {ar0, ar1, ar2};

    for (int i = tid; i < 3*2304; i += 256) {
        int gat = i / 2304, rem = i % 2304;
        int k = rem / 24, c4 = rem % 24;
        float4 v = reinterpret_cast<const float4*>(Wp[gat])[rem];
        *reinterpret_cast<uint4*>(&Ws[gat*96*104 + k*104 + c4*4]) =
            make_uint4(f2tf32(v.x), f2tf32(v.y), f2tf32(v.z), f2tf32(v.w));
    }
    for (int i = tid; i < 3072; i += 256) {
        int r = i / 24, c4 = i % 24;
        int gr = row0 + r;
        int n = gr / 96, k = gr % 96;
        int b = k & 3, t = k >> 2;
        int off = ((b*TT + t)*NN + n)*FF;
        float4 v = *reinterpret_cast<const float4*>(X + off + c4*4);
        float4 e = *reinterpret_cast<const float4*>(Emb + off + c4*4);
        v.x += e.x; v.y += e.y; v.z += e.z; v.w += e.w;
        *reinterpret_cast<float4*>(&Xs[r*100 + c4*4]) = v;
    }
    __syncthreads();

    const int lane = tid & 31, w = tid >> 5;
    const int g = lane >> 2, tig = lane & 3;
    const int r0 = w * 16;
    const int gr0 = row0 + r0 + g, gr1 = gr0 + 8;

    uint32_t af[12][4];
    #pragma unroll
    for (int ks = 0; ks < 12; ++ks) {
        int k0 = ks * 8;
        af[ks][0] = f2tf32(Xs[(r0+g  )*100 + k0 + tig    ]);
        af[ks][1] = f2tf32(Xs[(r0+g+8)*100 + k0 + tig    ]);
        af[ks][2] = f2tf32(Xs[(r0+g  )*100 + k0 + tig + 4]);
        af[ks][3] = f2tf32(Xs[(r0+g+8)*100 + k0 + tig + 4]);
    }

    for (int gat = 0; gat < 3; ++gat) {
        const uint32_t* Wg_ = Ws + gat*96*104;
        float acc[12][4];
        #pragma unroll
        for (int nt = 0; nt < 12; ++nt)
            #pragma unroll
            for (int q = 0; q < 4; ++q) acc[nt][q] = 0.f;
        #pragma unroll
        for (int ks = 0; ks < 12; ++ks) {
            int k0 = ks * 8;
            #pragma unroll
            for (int nt = 0; nt < 12; ++nt) {
                uint32_t b0 = Wg_[(k0+tig  )*104 + nt*8 + g];
                uint32_t b1 = Wg_[(k0+tig+4)*104 + nt*8 + g];
                mma_tf32(acc[nt], af[ks], b0, b1);
            }
        }
        // H stored fp16 (halves gat_agg2's gather traffic); el/er stay fp32.
        __half* Hb = g_h3 + (size_t)gat*RR*96;
        #pragma unroll
        for (int nt = 0; nt < 12; ++nt) {
            *reinterpret_cast<__half2*>(Hb + (size_t)gr0*96 + nt*8 + 2*tig) =
                __floats2half2_rn(acc[nt][0], acc[nt][1]);
            *reinterpret_cast<__half2*>(Hb + (size_t)gr1*96 + nt*8 + 2*tig) =
                __floats2half2_rn(acc[nt][2], acc[nt][3]);
        }
        const float* al = alp[gat];
        const float* ar = arp[gat];
        #pragma unroll
        for (int h = 0; h < 3; ++h) {
            float sl0 = 0.f, sr0 = 0.f, sl1 = 0.f, sr1 = 0.f;
            #pragma unroll
            for (int q = 0; q < 4; ++q) {
                int nt = h*4 + q;
                float a0 = al[nt*8 + 2*tig], a1 = al[nt*8 + 2*tig + 1];
                float c0 = ar[nt*8 + 2*tig], c1 = ar[nt*8 + 2*tig + 1];
                sl0 += acc[nt][0]*a0 + acc[nt][1]*a1;
                sr0 += acc[nt][0]*c0 + acc[nt][1]*c1;
                sl1 += acc[nt][2]*a0 + acc[nt][3]*a1;
                sr1 += acc[nt][2]*c0 + acc[nt][3]*c1;
            }
            sl0 += __shfl_xor_sync(0xffffffffu, sl0, 1); sl0 += __shfl_xor_sync(0xffffffffu, sl0, 2);
            sr0 += __shfl_xor_sync(0xffffffffu, sr0, 1); sr0 += __shfl_xor_sync(0xffffffffu, sr0, 2);
            sl1 += __shfl_xor_sync(0xffffffffu, sl1, 1); sl1 += __shfl_xor_sync(0xffffffffu, sl1, 2);
            sr1 += __shfl_xor_sync(0xffffffffu, sr1, 1); sr1 += __shfl_xor_sync(0xffffffffu, sr1, 2);
            if (tig == 0) {
                g_el3[(size_t)gat*RR*3 + gr0*3 + h] = sl0;
                g_er3[(size_t)gat*RR*3 + gr0*3 + h] = sr0;
                g_el3[(size_t)gat*RR*3 + gr1*3 + h] = sl1;
                g_er3[(size_t)gat*RR*3 + gr1*3 + h] = sr1;
            }
        }
    }
}

// =============== temporal projection GEMM (HEADS=4) ==========================
__global__ __launch_bounds__(256)
void gemm_tc_tp(const float* __restrict__ X, const float* __restrict__ W,
                const float* __restrict__ al, const float* __restrict__ ar)
{
    extern __shared__ float sm[];
    float*    Xs = sm;                                 // [128][100]
    uint32_t* Ws = (uint32_t*)(sm + 128*100);          // [96][104]
    const int tid = threadIdx.x;
    const int row0 = blockIdx.x * 128;

    for (int i = tid; i < 2304; i += 256) {
        int k = i / 24, c4 = i % 24;
        float4 v = reinterpret_cast<const float4*>(W)[i];
        *reinterpret_cast<uint4*>(&Ws[k*104 + c4*4]) =
            make_uint4(f2tf32(v.x), f2tf32(v.y), f2tf32(v.z), f2tf32(v.w));
    }
    for (int i = tid; i < 3072; i += 256) {
        int r = i / 24, c4 = i % 24;
        int gr = row0 + r;
        int rr = gr / 24, t = gr % 24;
        int b = rr >> 10, n = rr & 1023;
        int off = ((b*TT + t)*NN + n)*FF;
        *reinterpret_cast<float4*>(&Xs[r*100 + c4*4]) = *reinterpret_cast<const float4*>(X + off + c4*4);
    }
    __syncthreads();

    const int lane = tid & 31, w = tid >> 5;
    const int g = lane >> 2, tig = lane & 3;
    const int r0 = w * 16;
    float acc[12][4];
    #pragma unroll
    for (int nt = 0; nt < 12; ++nt)
        #pragma unroll
        for (int q = 0; q < 4; ++q) acc[nt][q] = 0.f;
    #pragma unroll
    for (int ks = 0; ks < 12; ++ks) {
        int k0 = ks * 8;
        uint32_t a[4];
        a[0] = f2tf32(Xs[(r0+g  )*100 + k0 + tig    ]);
        a[1] = f2tf32(Xs[(r0+g+8)*100 + k0 + tig    ]);
        a[2] = f2tf32(Xs[(r0+g  )*100 + k0 + tig + 4]);
        a[3] = f2tf32(Xs[(r0+g+8)*100 + k0 + tig + 4]);
        #pragma unroll
        for (int nt = 0; nt < 12; ++nt) {
            uint32_t b0 = Ws[(k0+tig  )*104 + nt*8 + g];
            uint32_t b1 = Ws[(k0+tig+4)*104 + nt*8 + g];
            mma_tf32(acc[nt], a, b0, b1);
        }
    }
    const int gr0 = row0 + r0 + g, gr1 = gr0 + 8;
    #pragma unroll
    for (int nt = 0; nt < 12; ++nt) {
        *reinterpret_cast<float2*>(g_hg + (size_t)gr0*96 + nt*8 + 2*tig) = make_float2(acc[nt][0], acc[nt][1]);
        *reinterpret_cast<float2*>(g_hg + (size_t)gr1*96 + nt*8 + 2*tig) = make_float2(acc[nt][2], acc[nt][3]);
    }
    #pragma unroll
    for (int h = 0; h < 4; ++h) {
        float sl0 = 0.f, sr0 = 0.f, sl1 = 0.f, sr1 = 0.f;
        #pragma unroll
        for (int q = 0; q < 3; ++q) {
            int nt = h*3 + q;
            float a0 = al[nt*8 + 2*tig], a1 = al[nt*8 + 2*tig + 1];
            float c0 = ar[nt*8 + 2*tig], c1 = ar[nt*8 + 2*tig + 1];
            sl0 += acc[nt][0]*a0 + acc[nt][1]*a1;
            sr0 += acc[nt][0]*c0 + acc[nt][1]*c1;
            sl1 += acc[nt][2]*a0 + acc[nt][3]*a1;
            sr1 += acc[nt][2]*c0 + acc[nt][3]*c1;
        }
        sl0 += __shfl_xor_sync(0xffffffffu, sl0, 1); sl0 += __shfl_xor_sync(0xffffffffu, sl0, 2);
        sr0 += __shfl_xor_sync(0xffffffffu, sr0, 1); sr0 += __shfl_xor_sync(0xffffffffu, sr0, 2);
        sl1 += __shfl_xor_sync(0xffffffffu, sl1, 1); sl1 += __shfl_xor_sync(0xffffffffu, sl1, 2);
        sr1 += __shfl_xor_sync(0xffffffffu, sr1, 1); sr1 += __shfl_xor_sync(0xffffffffu, sr1, 2);
        if (tig == 0) {
            g_elg[gr0*4 + h] = sl0;  g_erg[gr0*4 + h] = sr0;
            g_elg[gr1*4 + h] = sl1;  g_erg[gr1*4 + h] = sr1;
        }
    }
}

// ---------------- GAT aggregation v2: one block per (n, gat), fp16 H ---------
__global__ __launch_bounds__(256)
void gat_agg2(const int* __restrict__ src0, const int* __restrict__ src1,
              const int* __restrict__ src2,
              const float* __restrict__ bias0, const float* __restrict__ bias1,
              const float* __restrict__ bias2,
              const float* __restrict__ inp)
{
    const int gat = blockIdx.y, n = blockIdx.x, tid = threadIdx.x;
    const int*   src  = (gat == 0) ? src0  : (gat == 1) ? src1  : src2;
    const float* bias = (gat == 0) ? bias0 : (gat == 1) ? bias1 : bias2;
    const __half* H  = g_h3  + (size_t)gat*RR*96;
    const float* EL = g_el3 + (size_t)gat*RR*3;
    const float* ER = g_er3 + (size_t)gat*RR*3;

    __shared__ int   ssm[8];
    __shared__ float er_s[288];
    __shared__ float as[2304];      // [q = k*3+h][j]
    __shared__ float bsum[32];

    if (tid < 8)  ssm[tid] = src[n + tid*NN];
    if (tid < 32) bsum[tid] = bias[tid] + bias[32 + tid] + bias[64 + tid];
    for (int q = tid; q < 288; q += 256) er_s[q] = ER[n*288 + q];
    __syncthreads();

    for (int j = 0; j < 8; ++j) {
        const float* elp = EL + (size_t)ssm[j] * 288;
        for (int q = tid; q < 288; q += 256) {
            float x = elp[q] + er_s[q];
            as[q*8 + j] = (x >= 0.f) ? x : 0.2f*x;
        }
    }
    __syncthreads();
    for (int q = tid; q < 288; q += 256) {
        float e[8], m = -1e30f;
        #pragma unroll
        for (int j = 0; j < 8; ++j) { e[j] = as[q*8 + j]; m = fmaxf(m, e[j]); }
        float s = 0.f;
        #pragma unroll
        for (int j = 0; j < 8; ++j) { e[j] = expf(e[j] - m); s += e[j]; }
        float inv = 1.f / (s + 1e-9f);
        #pragma unroll
        for (int j = 0; j < 8; ++j) as[q*8 + j] = e[j] * inv;
    }
    __syncthreads();

    const int d = tid & 31, kg = tid >> 5;
    float acc[12];
    #pragma unroll
    for (int s = 0; s < 12; ++s) acc[s] = 0.f;
    for (int j = 0; j < 8; ++j) {
        const __half* hb = H + (size_t)ssm[j] * 96 * 96;
        #pragma unroll
        for (int s = 0; s < 12; ++s) {
            int k = kg + 8*s;
            const __half* hp = hb + k*96;
            float a0 = as[(k*3+0)*8 + j];
            float a1 = as[(k*3+1)*8 + j];
            float a2 = as[(k*3+2)*8 + j];
            acc[s] += a0*__half2float(hp[d]) + a1*__half2float(hp[32 + d]) + a2*__half2float(hp[64 + d]);
        }
    }
    #pragma unroll
    for (int s = 0; s < 12; ++s) {
        int k = kg + 8*s;
        float val = (acc[s] + bsum[d]) * (1.f/3.f);
        int ob = k / 24, ot = k % 24;      // reference's reshape scramble
        size_t o = (size_t)((ob*TT + ot)*NN + n)*FF + gat*32 + d;
        g_spatial[o] = inp[o] + val;
    }
}

// ---------------- attn_S = softmax(cov0 @ cov0^T, axis=2) -- fp32 ------------
__global__ __launch_bounds__(256)
void attnS_gemm(const float* __restrict__ spatE, float* __restrict__ Sout)
{
    extern __shared__ float sm2[];
    float* At = sm2;            // [64][97]
    float* Bt = sm2 + 64*97;    // [64][97]
    int b = blockIdx.z;
    int i0 = blockIdx.y * 64, j0 = blockIdx.x * 64;
    const float* cov = spatE + (size_t)b*TT*NN*FF;   // t = 0 slice
    int tid = threadIdx.x;       // 256
    #pragma unroll
    for (int i = 0; i < 6; ++i) {
        int idx = tid + i*256;   // < 1536
        int r = idx / 24, c4 = idx % 24;
        float4 v = *reinterpret_cast<const float4*>(cov + (i0 + r)*96 + c4*4);
        At[r*97 + c4*4+0] = v.x; At[r*97 + c4*4+1] = v.y;
        At[r*97 + c4*4+2] = v.z; At[r*97 + c4*4+3] = v.w;
        float4 w = *reinterpret_cast<const float4*>(cov + (j0 + r)*96 + c4*4);
        Bt[r*97 + c4*4+0] = w.x; Bt[r*97 + c4*4+1] = w.y;
        Bt[r*97 + c4*4+2] = w.z; Bt[r*97 + c4*4+3] = w.w;
    }
    __syncthreads();
    int tx = tid & 15, ty = tid >> 4;
    float acc[4][4];
    #pragma unroll
    for (int u = 0; u < 4; ++u)
        #pragma unroll
        for (int v = 0; v < 4; ++v) acc[u][v] = 0.f;
    #pragma unroll 8
    for (int f = 0; f < 96; ++f) {
        float a[4], bb[4];
        #pragma unroll
        for (int u = 0; u < 4; ++u) a[u] = At[(ty*4+u)*97 + f];
        #pragma unroll
        for (int v = 0; v < 4; ++v) bb[v] = Bt[(tx*4+v)*97 + f];
        #pragma unroll
        for (int u = 0; u < 4; ++u)
            #pragma unroll
            for (int v = 0; v < 4; ++v) acc[u][v] = fmaf(a[u], bb[v], acc[u][v]);
    }
    #pragma unroll
    for (int u = 0; u < 4; ++u) {
        float4 o = make_float4(acc[u][0], acc[u][1], acc[u][2], acc[u][3]);
        *reinterpret_cast<float4*>(Sout + ((size_t)b*NN + i0 + ty*4 + u)*NN + j0 + tx*4) = o;
    }
}

__global__ void rowsoftmax1024(float* __restrict__ S)
{
    int row = blockIdx.x;
    float* p = S + (size_t)row * 1024;
    int tid = threadIdx.x;   // 256
    float v[4];
    float m = -1e30f;
    #pragma unroll
    for (int q = 0; q < 4; ++q) { v[q] = p[tid + q*256]; m = fmaxf(m, v[q]); }
    __shared__ float red[8];
    __shared__ float red2[8];
    for (int o = 16; o >= 1; o >>= 1) m = fmaxf(m, __shfl_xor_sync(0xffffffffu, m, o));
    if ((tid & 31) == 0) red[tid >> 5] = m;
    __syncthreads();
    float mm = red[0];
    #pragma unroll
    for (int w = 1; w < 8; ++w) mm = fmaxf(mm, red[w]);
    float s = 0.f;
    #pragma unroll
    for (int q = 0; q < 4; ++q) { v[q] = expf(v[q] - mm); s += v[q]; }
    for (int o = 16; o >= 1; o >>= 1) s += __shfl_xor_sync(0xffffffffu, s, o);
    if ((tid & 31) == 0) red2[tid >> 5] = s;
    __syncthreads();
    float ss = 0.f;
    #pragma unroll
    for (int w = 0; w < 8; ++w) ss += red2[w];
    float inv = 1.f / ss;
    #pragma unroll
    for (int q = 0; q < 4; ++q) p[tid + q*256] = v[q] * inv;
}

// ---------------- attn_T = softmax(covT @ covT^T, axis=1) --------------------
__global__ void attnT_kernel(const float* __restrict__ tempE)
{
    __shared__ float cov[24][96];
    __shared__ float s[24][25];
    __shared__ float colmax[24], colsum[24];
    int b = blockIdx.x;
    int j = threadIdx.x, i = threadIdx.y;
    int tid = i*24 + j;
    for (int q = tid; q < 2304; q += 576) {
        int t = q / 96, f = q % 96;
        cov[t][f] = tempE[((b*TT + t)*NN)*FF + f];   // n = 0 slice
    }
    __syncthreads();
    float acc = 0.f;
    #pragma unroll
    for (int f = 0; f < 96; ++f) acc = fmaf(cov[i][f], cov[j][f], acc);
    s[i][j] = acc;
    __syncthreads();
    if (i == 0) {
        float m = -1e30f;
        for (int t = 0; t < 24; ++t) m = fmaxf(m, s[t][j]);
        colmax[j] = m;
    }
    __syncthreads();
    float e = expf(acc - colmax[j]);
    s[i][j] = e;
    __syncthreads();
    if (i == 0) {
        float sm0 = 0.f;
        for (int t = 0; t < 24; ++t) sm0 += s[t][j];
        colsum[j] = sm0;
    }
    __syncthreads();
    g_attnT[(b*TT + i)*TT + j] = e / colsum[j];
}

// ---------------- temporal branch v2: 288 threads, register-hoisted ----------
__global__ __launch_bounds__(288)
void temporal2(const float* __restrict__ input)
{
    __shared__ float hgs[2304];
    __shared__ float xts[2304];
    __shared__ float alph[2304];
    __shared__ float ats[576];
    __shared__ float elgs[96], ergs[96];
    int r = blockIdx.x;              // r = b*N + n
    int b = r >> 10, n = r & 1023;
    int tid = threadIdx.x;           // 288
    for (int q = tid; q < 2304; q += 288) hgs[q] = g_hg[(size_t)r*2304 + q];
    for (int q = tid; q < 2304; q += 288) {
        int t = q / 96, f = q % 96;
        xts[q] = input[((b*TT + t)*NN + n)*FF + f];
    }
    if (tid < 96) { elgs[tid] = g_elg[r*96 + tid]; ergs[tid] = g_erg[r*96 + tid]; }
    for (int q = tid; q < 576; q += 288) ats[q] = g_attnT[(n & 3)*576 + q]; // idx = r%B = n%4
    __syncthreads();
    if (tid < 96) {                  // softmax over j for (i,g)
        int i = tid >> 2, g = tid & 3;
        float eli = elgs[i*4 + g];
        float ev[24];
        float m = -1e30f;
        #pragma unroll
        for (int j = 0; j < 24; ++j) {
            float x = eli + ergs[j*4 + g];
            x = (x >= 0.f) ? x : 0.2f*x;
            ev[j] = x;
            m = fmaxf(m, x);
        }
        float s = 0.f;
        #pragma unroll
        for (int j = 0; j < 24; ++j) { ev[j] = expf(ev[j] - m); s += ev[j]; }
        float inv = 1.f / s;
        #pragma unroll
        for (int j = 0; j < 24; ++j) alph[tid*24 + j] = ev[j]*inv;
    }
    __syncthreads();

    int f = tid % 96, tr = tid / 96;       // tr 0..2
    int g = f / 24;
    float hv[24], xv[24];
    #pragma unroll
    for (int j = 0; j < 24; ++j) { hv[j] = hgs[j*96 + f]; xv[j] = xts[j*96 + f]; }
    #pragma unroll
    for (int s = 0; s < 8; ++s) {
        int i = tr + 3*s;
        float xa = 0.f, ea = 0.f;
        const float* ap = &alph[(i*4 + g)*24];
        const float* tp = &ats[i*24];
        #pragma unroll
        for (int j = 0; j < 24; ++j) {
            xa = fmaf(ap[j], hv[j], xa);
            ea = fmaf(tp[j], xv[j], ea);
        }
        float sg = 1.f / (1.f + expf(-ea));
        g_temporal[(size_t)((b*TT + i)*NN + n)*FF + f] = xv[i] + xa*sg;
    }
}

// ---------------- fusion (tensor-core): z = sigmoid([sp,tp]@Wf + bf) ---------
__global__ __launch_bounds__(256)
void fusion_tc(const float* __restrict__ input, const float* __restrict__ Wf,
               const float* __restrict__ bf, float* __restrict__ outp)
{
    extern __shared__ float sm[];
    float*    Xsp = sm;                                  // [128][100] fp32
    float*    Xtp = sm + 128*100;                        // [128][100] fp32
    uint32_t* Ws  = (uint32_t*)(sm + 2*128*100);         // [192][104] tf32

    const int tid = threadIdx.x;
    const int row0 = blockIdx.x * 128;

    for (int i = tid; i < 192*24; i += 256) {
        int k = i / 24, c4 = i % 24;
        float4 v = reinterpret_cast<const float4*>(Wf)[i];
        *reinterpret_cast<uint4*>(&Ws[k*104 + c4*4]) =
            make_uint4(f2tf32(v.x), f2tf32(v.y), f2tf32(v.z), f2tf32(v.w));
    }
    for (int i = tid; i < 3072; i += 256) {
        int r = i / 24, c4 = i % 24;
        size_t off = (size_t)(row0 + r)*96 + c4*4;
        *reinterpret_cast<float4*>(&Xsp[r*100 + c4*4]) = *reinterpret_cast<const float4*>(g_spatial + off);
        *reinterpret_cast<float4*>(&Xtp[r*100 + c4*4]) = *reinterpret_cast<const float4*>(g_temporal + off);
    }
    __syncthreads();

    const int lane = tid & 31, w = tid >> 5;
    const int g = lane >> 2, tig = lane & 3;
    const int r0 = w * 16;

    float acc[12][4];
    #pragma unroll
    for (int nt = 0; nt < 12; ++nt)
        #pragma unroll
        for (int q = 0; q < 4; ++q) acc[nt][q] = 0.f;

    #pragma unroll
    for (int ks = 0; ks < 12; ++ks) {           // spatial half (Wf rows 0..95)
        int k0 = ks * 8;
        uint32_t a[4];
        a[0] = f2tf32(Xsp[(r0+g  )*100 + k0 + tig    ]);
        a[1] = f2tf32(Xsp[(r0+g+8)*100 + k0 + tig    ]);
        a[2] = f2tf32(Xsp[(r0+g  )*100 + k0 + tig + 4]);
        a[3] = f2tf32(Xsp[(r0+g+8)*100 + k0 + tig + 4]);
        #pragma unroll
        for (int nt = 0; nt < 12; ++nt) {
            uint32_t b0 = Ws[(k0+tig  )*104 + nt*8 + g];
            uint32_t b1 = Ws[(k0+tig+4)*104 + nt*8 + g];
            mma_tf32(acc[nt], a, b0, b1);
        }
    }
    #pragma unroll
    for (int ks = 0; ks < 12; ++ks) {           // temporal half (Wf rows 96..191)
        int k0 = ks * 8;
        uint32_t a[4];
        a[0] = f2tf32(Xtp[(r0+g  )*100 + k0 + tig    ]);
        a[1] = f2tf32(Xtp[(r0+g+8)*100 + k0 + tig    ]);
        a[2] = f2tf32(Xtp[(r0+g  )*100 + k0 + tig + 4]);
        a[3] = f2tf32(Xtp[(r0+g+8)*100 + k0 + tig + 4]);
        #pragma unroll
        for (int nt = 0; nt < 12; ++nt) {
            uint32_t b0 = Ws[(96+k0+tig  )*104 + nt*8 + g];
            uint32_t b1 = Ws[(96+k0+tig+4)*104 + nt*8 + g];
            mma_tf32(acc[nt], a, b0, b1);
        }
    }

    const int gr0 = row0 + r0 + g, gr1 = gr0 + 8;
    const int rl0 = r0 + g, rl1 = rl0 + 8;
    #pragma unroll
    for (int nt = 0; nt < 12; ++nt) {
        int col = nt*8 + 2*tig;
        float b0v = bf[col], b1v = bf[col+1];
        float2 in0 = *reinterpret_cast<const float2*>(input + (size_t)gr0*96 + col);
        float2 in1 = *reinterpret_cast<const float2*>(input + (size_t)gr1*96 + col);
        float z00 = 1.f/(1.f+expf(-(acc[nt][0] + b0v)));
        float z01 = 1.f/(1.f+expf(-(acc[nt][1] + b1v)));
        float z10 = 1.f/(1.f+expf(-(acc[nt][2] + b0v)));
        float z11 = 1.f/(1.f+expf(-(acc[nt][3] + b1v)));
        float sp00 = Xsp[rl0*100 + col], sp01 = Xsp[rl0*100 + col + 1];
        float sp10 = Xsp[rl1*100 + col], sp11 = Xsp[rl1*100 + col + 1];
        float tp00 = Xtp[rl0*100 + col], tp01 = Xtp[rl0*100 + col + 1];
        float tp10 = Xtp[rl1*100 + col], tp11 = Xtp[rl1*100 + col + 1];
        float2 o0 = make_float2(z00*sp00 + (1.f-z00)*tp00 + in0.x,
                                z01*sp01 + (1.f-z01)*tp01 + in0.y);
        float2 o1 = make_float2(z10*sp10 + (1.f-z10)*tp10 + in1.x,
                                z11*sp11 + (1.f-z11)*tp11 + in1.y);
        *reinterpret_cast<float2*>(outp + (size_t)gr0*96 + col) = o0;
        *reinterpret_cast<float2*>(outp + (size_t)gr1*96 + col) = o1;
    }
}

extern "C" void kernel_launch(void* const* d_in, const int* in_sizes, int n_in,
                              void* d_out, int out_size)
{
    const float* input = (const float*)d_in[0];
    const float* spatE = (const float*)d_in[1];
    const float* tempE = (const float*)d_in[2];
    const int*   s0 = (const int*)d_in[3];
    const int*   s1 = (const int*)d_in[5];
    const int*   s2 = (const int*)d_in[7];
    const float* W_d = (const float*)d_in[9];
    const float* al_d = (const float*)d_in[10];
    const float* ar_d = (const float*)d_in[11];
    const float* b_d = (const float*)d_in[12];
    const float* W_m = (const float*)d_in[13];
    const float* al_m = (const float*)d_in[14];
    const float* ar_m = (const float*)d_in[15];
    const float* b_m = (const float*)d_in[16];
    const float* W_s = (const float*)d_in[17];
    const float* al_s = (const float*)d_in[18];
    const float* ar_s = (const float*)d_in[19];
    const float* b_s = (const float*)d_in[20];
    const float* Wg  = (const float*)d_in[21];
    const float* agl = (const float*)d_in[22];
    const float* agr = (const float*)d_in[23];
    const float* Wf  = (const float*)d_in[24];
    const float* bf  = (const float*)d_in[25];
    float* out   = (float*)d_out;
    float* attnS = out + (size_t)RR*96;   // out (B,T,N,F) then attn_S (B,N,N)

    const int SP_SMEM  = (128*100 + 3*96*104) * 4;         // 171,008 B
    const int TP_SMEM  = (128*100 + 96*104) * 4;           //  91,136 B
    const int FUS_SMEM = (2*128*100 + 192*104) * 4;        // 182,272 B
    const int ATS_SMEM = (2*64*97) * 4;                    //  49,664 B

    static cudaStream_t stB = 0, stC = 0;
    static cudaEvent_t evFork = 0, evB = 0, evC = 0;
    static int inited = 0;
    static int use_streams = 0;
    if (!inited) {
        cudaFuncSetAttribute(gemm_tc_sp, cudaFuncAttributeMaxDynamicSharedMemorySize, SP_SMEM);
        cudaFuncSetAttribute(gemm_tc_tp, cudaFuncAttributeMaxDynamicSharedMemorySize, TP_SMEM);
        cudaFuncSetAttribute(fusion_tc,  cudaFuncAttributeMaxDynamicSharedMemorySize, FUS_SMEM);
        cudaFuncSetAttribute(attnS_gemm, cudaFuncAttributeMaxDynamicSharedMemorySize, ATS_SMEM);
        use_streams = 1;
        if (cudaStreamCreateWithFlags(&stB, cudaStreamNonBlocking) != cudaSuccess) use_streams = 0;
        if (use_streams && cudaStreamCreateWithFlags(&stC, cudaStreamNonBlocking) != cudaSuccess) use_streams = 0;
        if (use_streams && cudaEventCreateWithFlags(&evFork, cudaEventDisableTiming) != cudaSuccess) use_streams = 0;
        if (use_streams && cudaEventCreateWithFlags(&evB,    cudaEventDisableTiming) != cudaSuccess) use_streams = 0;
        if (use_streams && cudaEventCreateWithFlags(&evC,    cudaEventDisableTiming) != cudaSuccess) use_streams = 0;
        inited = 1;
    }

    if (use_streams) {
        cudaStreamCaptureMode mode = cudaStreamCaptureModeRelaxed;
        cudaThreadExchangeStreamCaptureMode(&mode);

        cudaEventRecord(evFork, 0);
        cudaStreamWaitEvent(stB, evFork, 0);
        cudaStreamWaitEvent(stC, evFork, 0);

        // chain A first (critical path): spatial GEMM (3 gats) -> aggregation
        gemm_tc_sp<<<RGRID, 256, SP_SMEM>>>(input, spatE,
            W_d, W_m, W_s, al_d, al_m, al_s, ar_d, ar_m, ar_s);
        gat_agg2<<<dim3(NN, 3), 256>>>(s0, s1, s2, b_d, b_m, b_s, input);

        // chain B: temporal projection -> attn_T -> temporal branch
        gemm_tc_tp<<<RGRID, 256, TP_SMEM, stB>>>(input, Wg, agl, agr);
        attnT_kernel<<<4, dim3(24,24), 0, stB>>>(tempE);
        temporal2<<<4096, 288, 0, stB>>>(input);
        cudaEventRecord(evB, stB);

        // chain C: attn_S output (independent)
        attnS_gemm<<<dim3(16,16,4), 256, ATS_SMEM, stC>>>(spatE, attnS);
        rowsoftmax1024<<<4096, 256, 0, stC>>>(attnS);
        cudaEventRecord(evC, stC);

        cudaStreamWaitEvent(0, evB, 0);
        fusion_tc<<<RGRID, 256, FUS_SMEM>>>(input, Wf, bf, out);
        cudaStreamWaitEvent(0, evC, 0);

        cudaThreadExchangeStreamCaptureMode(&mode);   // restore
    } else {
        // sequential fallback
        gemm_tc_sp<<<RGRID, 256, SP_SMEM>>>(input, spatE,
            W_d, W_m, W_s, al_d, al_m, al_s, ar_d, ar_m, ar_s);
        gemm_tc_tp<<<RGRID, 256, TP_SMEM>>>(input, Wg, agl, agr);
        gat_agg2<<<dim3(NN, 3), 256>>>(s0, s1, s2, b_d, b_m, b_s, input);
        attnS_gemm<<<dim3(16,16,4), 256, ATS_SMEM>>>(spatE, attnS);
        rowsoftmax1024<<<4096, 256>>>(attnS);
        attnT_kernel<<<4, dim3(24,24)>>>(tempE);
        temporal2<<<4096, 288>>>(input);
        fusion_tc<<<RGRID, 256, FUS_SMEM>>>(input, Wf, bf, out);
    }
}

// round 14
// speedup vs baseline: 1.0718x; 1.0718x over previous
#include <cuda_runtime.h>
#include <cuda_fp16.h>
#include <math.h>
#include <stdint.h>

#define NN 1024
#define BB 4
#define TT 24
#define FF 96
#define RR (NN*96)       // 98304 rows (== B*T*N)
#define RGRID (RR/128)   // 768

// ---------------- scratch (device globals; no allocs allowed) ----------------
__device__ __half g_h3[3*(size_t)RR*96];  // spatial GAT h (fp16), per gat
__device__ float g_el3[3*RR*3];
__device__ float g_er3[3*RR*3];
__device__ float g_hg[(size_t)RR*96];     // temporal hg (fp32), row = (b*N+n)*24+t
__device__ float g_elg[RR*4];
__device__ float g_erg[RR*4];
__device__ float g_spatial[(size_t)RR*96];
__device__ float g_temporal[(size_t)RR*96];
__device__ float g_attnT[BB*TT*TT];

// ---------------- tf32 helpers ----------------
__device__ __forceinline__ uint32_t f2tf32(float x) {
    uint32_t r; asm("cvt.rna.tf32.f32 %0, %1;" : "=r"(r) : "f"(x)); return r;
}
__device__ __forceinline__ void mma_tf32(float* c, const uint32_t* a, uint32_t b0, uint32_t b1) {
    asm volatile("mma.sync.aligned.m16n8k8.row.col.f32.tf32.tf32.f32 "
        "{%0,%1,%2,%3}, {%4,%5,%6,%7}, {%8,%9}, {%0,%1,%2,%3};"
        : "+f"(c[0]), "+f"(c[1]), "+f"(c[2]), "+f"(c[3])
        : "r"(a[0]), "r"(a[1]), "r"(a[2]), "r"(a[3]), "r"(b0), "r"(b1));
}

// =============== spatial GEMM: 128 rows x 96 cols, ALL 3 GATs per block ======
__global__ __launch_bounds__(256)
void gemm_tc_sp(const float* __restrict__ X, const float* __restrict__ Emb,
                const float* __restrict__ W0, const float* __restrict__ W1, const float* __restrict__ W2,
                const float* __restrict__ al0, const float* __restrict__ al1, const float* __restrict__ al2,
                const float* __restrict__ ar0, const float* __restrict__ ar1, const float* __restrict__ ar2)
{
    extern __shared__ float sm[];
    float*    Xs = sm;                                 // [128][100] fp32
    uint32_t* Ws = (uint32_t*)(sm + 128*100);          // 3 x [96][104] tf32

    const int tid = threadIdx.x;
    const int row0 = blockIdx.x * 128;
    const float* Wp[3]  = {W0, W1, W2};
    const float* alp[3] = {al0, al1, al2};
    const float* arp[3] = {ar0, ar1, ar2};

    for (int i = tid; i < 3*2304; i += 256) {
        int gat = i / 2304, rem = i % 2304;
        int k = rem / 24, c4 = rem % 24;
        float4 v = reinterpret_cast<const float4*>(Wp[gat])[rem];
        *reinterpret_cast<uint4*>(&Ws[gat*96*104 + k*104 + c4*4]) =
            make_uint4(f2tf32(v.x), f2tf32(v.y), f2tf32(v.z), f2tf32(v.w));
    }
    for (int i = tid; i < 3072; i += 256) {
        int r = i / 24, c4 = i % 24;
        int gr = row0 + r;
        int n = gr / 96, k = gr % 96;
        int b = k & 3, t = k >> 2;
        int off = ((b*TT + t)*NN + n)*FF;
        float4 v = *reinterpret_cast<const float4*>(X + off + c4*4);
        float4 e = *reinterpret_cast<const float4*>(Emb + off + c4*4);
        v.x += e.x; v.y += e.y; v.z += e.z; v.w += e.w;
        *reinterpret_cast<float4*>(&Xs[r*100 + c4*4]) = v;
    }
    __syncthreads();

    const int lane = tid & 31, w = tid >> 5;
    const int g = lane >> 2, tig = lane & 3;
    const int r0 = w * 16;
    const int gr0 = row0 + r0 + g, gr1 = gr0 + 8;

    uint32_t af[12][4];
    #pragma unroll
    for (int ks = 0; ks < 12; ++ks) {
        int k0 = ks * 8;
        af[ks][0] = f2tf32(Xs[(r0+g  )*100 + k0 + tig    ]);
        af[ks][1] = f2tf32(Xs[(r0+g+8)*100 + k0 + tig    ]);
        af[ks][2] = f2tf32(Xs[(r0+g  )*100 + k0 + tig + 4]);
        af[ks][3] = f2tf32(Xs[(r0+g+8)*100 + k0 + tig + 4]);
    }

    for (int gat = 0; gat < 3; ++gat) {
        const uint32_t* Wg_ = Ws + gat*96*104;
        float acc[12][4];
        #pragma unroll
        for (int nt = 0; nt < 12; ++nt)
            #pragma unroll
            for (int q = 0; q < 4; ++q) acc[nt][q] = 0.f;
        #pragma unroll
        for (int ks = 0; ks < 12; ++ks) {
            int k0 = ks * 8;
            #pragma unroll
            for (int nt = 0; nt < 12; ++nt) {
                uint32_t b0 = Wg_[(k0+tig  )*104 + nt*8 + g];
                uint32_t b1 = Wg_[(k0+tig+4)*104 + nt*8 + g];
                mma_tf32(acc[nt], af[ks], b0, b1);
            }
        }
        // H stored fp16; el/er stay fp32.
        __half* Hb = g_h3 + (size_t)gat*RR*96;
        #pragma unroll
        for (int nt = 0; nt < 12; ++nt) {
            *reinterpret_cast<__half2*>(Hb + (size_t)gr0*96 + nt*8 + 2*tig) =
                __floats2half2_rn(acc[nt][0], acc[nt][1]);
            *reinterpret_cast<__half2*>(Hb + (size_t)gr1*96 + nt*8 + 2*tig) =
                __floats2half2_rn(acc[nt][2], acc[nt][3]);
        }
        const float* al = alp[gat];
        const float* ar = arp[gat];
        #pragma unroll
        for (int h = 0; h < 3; ++h) {
            float sl0 = 0.f, sr0 = 0.f, sl1 = 0.f, sr1 = 0.f;
            #pragma unroll
            for (int q = 0; q < 4; ++q) {
                int nt = h*4 + q;
                float a0 = al[nt*8 + 2*tig], a1 = al[nt*8 + 2*tig + 1];
                float c0 = ar[nt*8 + 2*tig], c1 = ar[nt*8 + 2*tig + 1];
                sl0 += acc[nt][0]*a0 + acc[nt][1]*a1;
                sr0 += acc[nt][0]*c0 + acc[nt][1]*c1;
                sl1 += acc[nt][2]*a0 + acc[nt][3]*a1;
                sr1 += acc[nt][2]*c0 + acc[nt][3]*c1;
            }
            sl0 += __shfl_xor_sync(0xffffffffu, sl0, 1); sl0 += __shfl_xor_sync(0xffffffffu, sl0, 2);
            sr0 += __shfl_xor_sync(0xffffffffu, sr0, 1); sr0 += __shfl_xor_sync(0xffffffffu, sr0, 2);
            sl1 += __shfl_xor_sync(0xffffffffu, sl1, 1); sl1 += __shfl_xor_sync(0xffffffffu, sl1, 2);
            sr1 += __shfl_xor_sync(0xffffffffu, sr1, 1); sr1 += __shfl_xor_sync(0xffffffffu, sr1, 2);
            if (tig == 0) {
                g_el3[(size_t)gat*RR*3 + gr0*3 + h] = sl0;
                g_er3[(size_t)gat*RR*3 + gr0*3 + h] = sr0;
                g_el3[(size_t)gat*RR*3 + gr1*3 + h] = sl1;
                g_er3[(size_t)gat*RR*3 + gr1*3 + h] = sr1;
            }
        }
    }
}

// =============== temporal projection GEMM (HEADS=4) ==========================
__global__ __launch_bounds__(256)
void gemm_tc_tp(const float* __restrict__ X, const float* __restrict__ W,
                const float* __restrict__ al, const float* __restrict__ ar)
{
    extern __shared__ float sm[];
    float*    Xs = sm;                                 // [128][100]
    uint32_t* Ws = (uint32_t*)(sm + 128*100);          // [96][104]
    const int tid = threadIdx.x;
    const int row0 = blockIdx.x * 128;

    for (int i = tid; i < 2304; i += 256) {
        int k = i / 24, c4 = i % 24;
        float4 v = reinterpret_cast<const float4*>(W)[i];
        *reinterpret_cast<uint4*>(&Ws[k*104 + c4*4]) =
            make_uint4(f2tf32(v.x), f2tf32(v.y), f2tf32(v.z), f2tf32(v.w));
    }
    for (int i = tid; i < 3072; i += 256) {
        int r = i / 24, c4 = i % 24;
        int gr = row0 + r;
        int rr = gr / 24, t = gr % 24;
        int b = rr >> 10, n = rr & 1023;
        int off = ((b*TT + t)*NN + n)*FF;
        *reinterpret_cast<float4*>(&Xs[r*100 + c4*4]) = *reinterpret_cast<const float4*>(X + off + c4*4);
    }
    __syncthreads();

    const int lane = tid & 31, w = tid >> 5;
    const int g = lane >> 2, tig = lane & 3;
    const int r0 = w * 16;
    float acc[12][4];
    #pragma unroll
    for (int nt = 0; nt < 12; ++nt)
        #pragma unroll
        for (int q = 0; q < 4; ++q) acc[nt][q] = 0.f;
    #pragma unroll
    for (int ks = 0; ks < 12; ++ks) {
        int k0 = ks * 8;
        uint32_t a[4];
        a[0] = f2tf32(Xs[(r0+g  )*100 + k0 + tig    ]);
        a[1] = f2tf32(Xs[(r0+g+8)*100 + k0 + tig    ]);
        a[2] = f2tf32(Xs[(r0+g  )*100 + k0 + tig + 4]);
        a[3] = f2tf32(Xs[(r0+g+8)*100 + k0 + tig + 4]);
        #pragma unroll
        for (int nt = 0; nt < 12; ++nt) {
            uint32_t b0 = Ws[(k0+tig  )*104 + nt*8 + g];
            uint32_t b1 = Ws[(k0+tig+4)*104 + nt*8 + g];
            mma_tf32(acc[nt], a, b0, b1);
        }
    }
    const int gr0 = row0 + r0 + g, gr1 = gr0 + 8;
    #pragma unroll
    for (int nt = 0; nt < 12; ++nt) {
        *reinterpret_cast<float2*>(g_hg + (size_t)gr0*96 + nt*8 + 2*tig) = make_float2(acc[nt][0], acc[nt][1]);
        *reinterpret_cast<float2*>(g_hg + (size_t)gr1*96 + nt*8 + 2*tig) = make_float2(acc[nt][2], acc[nt][3]);
    }
    #pragma unroll
    for (int h = 0; h < 4; ++h) {
        float sl0 = 0.f, sr0 = 0.f, sl1 = 0.f, sr1 = 0.f;
        #pragma unroll
        for (int q = 0; q < 3; ++q) {
            int nt = h*3 + q;
            float a0 = al[nt*8 + 2*tig], a1 = al[nt*8 + 2*tig + 1];
            float c0 = ar[nt*8 + 2*tig], c1 = ar[nt*8 + 2*tig + 1];
            sl0 += acc[nt][0]*a0 + acc[nt][1]*a1;
            sr0 += acc[nt][0]*c0 + acc[nt][1]*c1;
            sl1 += acc[nt][2]*a0 + acc[nt][3]*a1;
            sr1 += acc[nt][2]*c0 + acc[nt][3]*c1;
        }
        sl0 += __shfl_xor_sync(0xffffffffu, sl0, 1); sl0 += __shfl_xor_sync(0xffffffffu, sl0, 2);
        sr0 += __shfl_xor_sync(0xffffffffu, sr0, 1); sr0 += __shfl_xor_sync(0xffffffffu, sr0, 2);
        sl1 += __shfl_xor_sync(0xffffffffu, sl1, 1); sl1 += __shfl_xor_sync(0xffffffffu, sl1, 2);
        sr1 += __shfl_xor_sync(0xffffffffu, sr1, 1); sr1 += __shfl_xor_sync(0xffffffffu, sr1, 2);
        if (tig == 0) {
            g_elg[gr0*4 + h] = sl0;  g_erg[gr0*4 + h] = sr0;
            g_elg[gr1*4 + h] = sl1;  g_erg[gr1*4 + h] = sr1;
        }
    }
}

// -------- GAT aggregation v3: half2 gather, thread = (dd 0..15, kg 0..15) ----
// Halves the LDG/STG instruction (L1-wavefront) count vs v2's scalar gather.
__global__ __launch_bounds__(256)
void gat_agg3(const int* __restrict__ src0, const int* __restrict__ src1,
              const int* __restrict__ src2,
              const float* __restrict__ bias0, const float* __restrict__ bias1,
              const float* __restrict__ bias2,
              const float* __restrict__ inp)
{
    const int gat = blockIdx.y, n = blockIdx.x, tid = threadIdx.x;
    const int*   src  = (gat == 0) ? src0  : (gat == 1) ? src1  : src2;
    const float* bias = (gat == 0) ? bias0 : (gat == 1) ? bias1 : bias2;
    const __half* H  = g_h3  + (size_t)gat*RR*96;
    const float* EL = g_el3 + (size_t)gat*RR*3;
    const float* ER = g_er3 + (size_t)gat*RR*3;

    __shared__ int   ssm[8];
    __shared__ float er_s[288];
    __shared__ float as[2304];      // [q = k*3+h][j]
    __shared__ float bsum[32];

    if (tid < 8)  ssm[tid] = src[n + tid*NN];
    if (tid < 32) bsum[tid] = bias[tid] + bias[32 + tid] + bias[64 + tid];
    for (int q = tid; q < 288; q += 256) er_s[q] = ER[n*288 + q];
    __syncthreads();

    for (int j = 0; j < 8; ++j) {
        const float* elp = EL + (size_t)ssm[j] * 288;
        for (int q = tid; q < 288; q += 256) {
            float x = elp[q] + er_s[q];
            as[q*8 + j] = (x >= 0.f) ? x : 0.2f*x;
        }
    }
    __syncthreads();
    for (int q = tid; q < 288; q += 256) {
        float e[8], m = -1e30f;
        #pragma unroll
        for (int j = 0; j < 8; ++j) { e[j] = as[q*8 + j]; m = fmaxf(m, e[j]); }
        float s = 0.f;
        #pragma unroll
        for (int j = 0; j < 8; ++j) { e[j] = expf(e[j] - m); s += e[j]; }
        float inv = 1.f / (s + 1e-9f);
        #pragma unroll
        for (int j = 0; j < 8; ++j) as[q*8 + j] = e[j] * inv;
    }
    __syncthreads();

    // thread = (dd, kg): d = 2*dd, 2*dd+1; 6 k's per thread (k = kg + 16*s)
    const int dd = tid & 15, kg = tid >> 4;
    float2 acc[6];
    #pragma unroll
    for (int s = 0; s < 6; ++s) acc[s] = make_float2(0.f, 0.f);
    for (int j = 0; j < 8; ++j) {
        const __half2* hb2 = reinterpret_cast<const __half2*>(H + (size_t)ssm[j] * 96 * 96);
        #pragma unroll
        for (int s = 0; s < 6; ++s) {
            int k = kg + 16*s;
            const __half2* hp2 = hb2 + k*48;          // row of 48 half2
            float a0 = as[(k*3+0)*8 + j];
            float a1 = as[(k*3+1)*8 + j];
            float a2 = as[(k*3+2)*8 + j];
            float2 h0 = __half22float2(hp2[dd]);
            float2 h1 = __half22float2(hp2[16 + dd]);
            float2 h2 = __half22float2(hp2[32 + dd]);
            acc[s].x += a0*h0.x + a1*h1.x + a2*h2.x;
            acc[s].y += a0*h0.y + a1*h1.y + a2*h2.y;
        }
    }
    float b0v = bsum[2*dd], b1v = bsum[2*dd + 1];
    #pragma unroll
    for (int s = 0; s < 6; ++s) {
        int k = kg + 16*s;
        float vx = (acc[s].x + b0v) * (1.f/3.f);
        float vy = (acc[s].y + b1v) * (1.f/3.f);
        int ob = k / 24, ot = k % 24;      // reference's reshape scramble
        size_t o = (size_t)((ob*TT + ot)*NN + n)*FF + gat*32 + 2*dd;
        float2 iv = *reinterpret_cast<const float2*>(inp + o);
        *reinterpret_cast<float2*>(g_spatial + o) = make_float2(iv.x + vx, iv.y + vy);
    }
}

// ---------------- attn_S = softmax(cov0 @ cov0^T, axis=2) -- fp32 ------------
__global__ __launch_bounds__(256)
void attnS_gemm(const float* __restrict__ spatE, float* __restrict__ Sout)
{
    extern __shared__ float sm2[];
    float* At = sm2;            // [64][97]
    float* Bt = sm2 + 64*97;    // [64][97]
    int b = blockIdx.z;
    int i0 = blockIdx.y * 64, j0 = blockIdx.x * 64;
    const float* cov = spatE + (size_t)b*TT*NN*FF;   // t = 0 slice
    int tid = threadIdx.x;       // 256
    #pragma unroll
    for (int i = 0; i < 6; ++i) {
        int idx = tid + i*256;   // < 1536
        int r = idx / 24, c4 = idx % 24;
        float4 v = *reinterpret_cast<const float4*>(cov + (i0 + r)*96 + c4*4);
        At[r*97 + c4*4+0] = v.x; At[r*97 + c4*4+1] = v.y;
        At[r*97 + c4*4+2] = v.z; At[r*97 + c4*4+3] = v.w;
        float4 w = *reinterpret_cast<const float4*>(cov + (j0 + r)*96 + c4*4);
        Bt[r*97 + c4*4+0] = w.x; Bt[r*97 + c4*4+1] = w.y;
        Bt[r*97 + c4*4+2] = w.z; Bt[r*97 + c4*4+3] = w.w;
    }
    __syncthreads();
    int tx = tid & 15, ty = tid >> 4;
    float acc[4][4];
    #pragma unroll
    for (int u = 0; u < 4; ++u)
        #pragma unroll
        for (int v = 0; v < 4; ++v) acc[u][v] = 0.f;
    #pragma unroll 8
    for (int f = 0; f < 96; ++f) {
        float a[4], bb[4];
        #pragma unroll
        for (int u = 0; u < 4; ++u) a[u] = At[(ty*4+u)*97 + f];
        #pragma unroll
        for (int v = 0; v < 4; ++v) bb[v] = Bt[(tx*4+v)*97 + f];
        #pragma unroll
        for (int u = 0; u < 4; ++u)
            #pragma unroll
            for (int v = 0; v < 4; ++v) acc[u][v] = fmaf(a[u], bb[v], acc[u][v]);
    }
    #pragma unroll
    for (int u = 0; u < 4; ++u) {
        float4 o = make_float4(acc[u][0], acc[u][1], acc[u][2], acc[u][3]);
        *reinterpret_cast<float4*>(Sout + ((size_t)b*NN + i0 + ty*4 + u)*NN + j0 + tx*4) = o;
    }
}

__global__ void rowsoftmax1024(float* __restrict__ S)
{
    int row = blockIdx.x;
    float* p = S + (size_t)row * 1024;
    int tid = threadIdx.x;   // 256
    float v[4];
    float m = -1e30f;
    #pragma unroll
    for (int q = 0; q < 4; ++q) { v[q] = p[tid + q*256]; m = fmaxf(m, v[q]); }
    __shared__ float red[8];
    __shared__ float red2[8];
    for (int o = 16; o >= 1; o >>= 1) m = fmaxf(m, __shfl_xor_sync(0xffffffffu, m, o));
    if ((tid & 31) == 0) red[tid >> 5] = m;
    __syncthreads();
    float mm = red[0];
    #pragma unroll
    for (int w = 1; w < 8; ++w) mm = fmaxf(mm, red[w]);
    float s = 0.f;
    #pragma unroll
    for (int q = 0; q < 4; ++q) { v[q] = expf(v[q] - mm); s += v[q]; }
    for (int o = 16; o >= 1; o >>= 1) s += __shfl_xor_sync(0xffffffffu, s, o);
    if ((tid & 31) == 0) red2[tid >> 5] = s;
    __syncthreads();
    float ss = 0.f;
    #pragma unroll
    for (int w = 0; w < 8; ++w) ss += red2[w];
    float inv = 1.f / ss;
    #pragma unroll
    for (int q = 0; q < 4; ++q) p[tid + q*256] = v[q] * inv;
}

// ---------------- attn_T = softmax(covT @ covT^T, axis=1) --------------------
__global__ void attnT_kernel(const float* __restrict__ tempE)
{
    __shared__ float cov[24][96];
    __shared__ float s[24][25];
    __shared__ float colmax[24], colsum[24];
    int b = blockIdx.x;
    int j = threadIdx.x, i = threadIdx.y;
    int tid = i*24 + j;
    for (int q = tid; q < 2304; q += 576) {
        int t = q / 96, f = q % 96;
        cov[t][f] = tempE[((b*TT + t)*NN)*FF + f];   // n = 0 slice
    }
    __syncthreads();
    float acc = 0.f;
    #pragma unroll
    for (int f = 0; f < 96; ++f) acc = fmaf(cov[i][f], cov[j][f], acc);
    s[i][j] = acc;
    __syncthreads();
    if (i == 0) {
        float m = -1e30f;
        for (int t = 0; t < 24; ++t) m = fmaxf(m, s[t][j]);
        colmax[j] = m;
    }
    __syncthreads();
    float e = expf(acc - colmax[j]);
    s[i][j] = e;
    __syncthreads();
    if (i == 0) {
        float sm0 = 0.f;
        for (int t = 0; t < 24; ++t) sm0 += s[t][j];
        colsum[j] = sm0;
    }
    __syncthreads();
    g_attnT[(b*TT + i)*TT + j] = e / colsum[j];
}

// ---------------- temporal branch v2: 288 threads, register-hoisted ----------
__global__ __launch_bounds__(288)
void temporal2(const float* __restrict__ input)
{
    __shared__ float hgs[2304];
    __shared__ float xts[2304];
    __shared__ float alph[2304];
    __shared__ float ats[576];
    __shared__ float elgs[96], ergs[96];
    int r = blockIdx.x;              // r = b*N + n
    int b = r >> 10, n = r & 1023;
    int tid = threadIdx.x;           // 288
    for (int q = tid; q < 2304; q += 288) hgs[q] = g_hg[(size_t)r*2304 + q];
    for (int q = tid; q < 2304; q += 288) {
        int t = q / 96, f = q % 96;
        xts[q] = input[((b*TT + t)*NN + n)*FF + f];
    }
    if (tid < 96) { elgs[tid] = g_elg[r*96 + tid]; ergs[tid] = g_erg[r*96 + tid]; }
    for (int q = tid; q < 576; q += 288) ats[q] = g_attnT[(n & 3)*576 + q]; // idx = r%B = n%4
    __syncthreads();
    if (tid < 96) {                  // softmax over j for (i,g)
        int i = tid >> 2, g = tid & 3;
        float eli = elgs[i*4 + g];
        float ev[24];
        float m = -1e30f;
        #pragma unroll
        for (int j = 0; j < 24; ++j) {
            float x = eli + ergs[j*4 + g];
            x = (x >= 0.f) ? x : 0.2f*x;
            ev[j] = x;
            m = fmaxf(m, x);
        }
        float s = 0.f;
        #pragma unroll
        for (int j = 0; j < 24; ++j) { ev[j] = expf(ev[j] - m); s += ev[j]; }
        float inv = 1.f / s;
        #pragma unroll
        for (int j = 0; j < 24; ++j) alph[tid*24 + j] = ev[j]*inv;
    }
    __syncthreads();

    int f = tid % 96, tr = tid / 96;       // tr 0..2
    int g = f / 24;
    float hv[24], xv[24];
    #pragma unroll
    for (int j = 0; j < 24; ++j) { hv[j] = hgs[j*96 + f]; xv[j] = xts[j*96 + f]; }
    #pragma unroll
    for (int s = 0; s < 8; ++s) {
        int i = tr + 3*s;
        float xa = 0.f, ea = 0.f;
        const float* ap = &alph[(i*4 + g)*24];
        const float* tp = &ats[i*24];
        #pragma unroll
        for (int j = 0; j < 24; ++j) {
            xa = fmaf(ap[j], hv[j], xa);
            ea = fmaf(tp[j], xv[j], ea);
        }
        float sg = 1.f / (1.f + expf(-ea));
        g_temporal[(size_t)((b*TT + i)*NN + n)*FF + f] = xv[i] + xa*sg;
    }
}

// ---------------- fusion (tensor-core): z = sigmoid([sp,tp]@Wf + bf) ---------
__global__ __launch_bounds__(256)
void fusion_tc(const float* __restrict__ input, const float* __restrict__ Wf,
               const float* __restrict__ bf, float* __restrict__ outp)
{
    extern __shared__ float sm[];
    float*    Xsp = sm;                                  // [128][100] fp32
    float*    Xtp = sm + 128*100;                        // [128][100] fp32
    uint32_t* Ws  = (uint32_t*)(sm + 2*128*100);         // [192][104] tf32

    const int tid = threadIdx.x;
    const int row0 = blockIdx.x * 128;

    for (int i = tid; i < 192*24; i += 256) {
        int k = i / 24, c4 = i % 24;
        float4 v = reinterpret_cast<const float4*>(Wf)[i];
        *reinterpret_cast<uint4*>(&Ws[k*104 + c4*4]) =
            make_uint4(f2tf32(v.x), f2tf32(v.y), f2tf32(v.z), f2tf32(v.w));
    }
    for (int i = tid; i < 3072; i += 256) {
        int r = i / 24, c4 = i % 24;
        size_t off = (size_t)(row0 + r)*96 + c4*4;
        *reinterpret_cast<float4*>(&Xsp[r*100 + c4*4]) = *reinterpret_cast<const float4*>(g_spatial + off);
        *reinterpret_cast<float4*>(&Xtp[r*100 + c4*4]) = *reinterpret_cast<const float4*>(g_temporal + off);
    }
    __syncthreads();

    const int lane = tid & 31, w = tid >> 5;
    const int g = lane >> 2, tig = lane & 3;
    const int r0 = w * 16;

    float acc[12][4];
    #pragma unroll
    for (int nt = 0; nt < 12; ++nt)
        #pragma unroll
        for (int q = 0; q < 4; ++q) acc[nt][q] = 0.f;

    #pragma unroll
    for (int ks = 0; ks < 12; ++ks) {           // spatial half (Wf rows 0..95)
        int k0 = ks * 8;
        uint32_t a[4];
        a[0] = f2tf32(Xsp[(r0+g  )*100 + k0 + tig    ]);
        a[1] = f2tf32(Xsp[(r0+g+8)*100 + k0 + tig    ]);
        a[2] = f2tf32(Xsp[(r0+g  )*100 + k0 + tig + 4]);
        a[3] = f2tf32(Xsp[(r0+g+8)*100 + k0 + tig + 4]);
        #pragma unroll
        for (int nt = 0; nt < 12; ++nt) {
            uint32_t b0 = Ws[(k0+tig  )*104 + nt*8 + g];
            uint32_t b1 = Ws[(k0+tig+4)*104 + nt*8 + g];
            mma_tf32(acc[nt], a, b0, b1);
        }
    }
    #pragma unroll
    for (int ks = 0; ks < 12; ++ks) {           // temporal half (Wf rows 96..191)
        int k0 = ks * 8;
        uint32_t a[4];
        a[0] = f2tf32(Xtp[(r0+g  )*100 + k0 + tig    ]);
        a[1] = f2tf32(Xtp[(r0+g+8)*100 + k0 + tig    ]);
        a[2] = f2tf32(Xtp[(r0+g  )*100 + k0 + tig + 4]);
        a[3] = f2tf32(Xtp[(r0+g+8)*100 + k0 + tig + 4]);
        #pragma unroll
        for (int nt = 0; nt < 12; ++nt) {
            uint32_t b0 = Ws[(96+k0+tig  )*104 + nt*8 + g];
            uint32_t b1 = Ws[(96+k0+tig+4)*104 + nt*8 + g];
            mma_tf32(acc[nt], a, b0, b1);
        }
    }

    const int gr0 = row0 + r0 + g, gr1 = gr0 + 8;
    const int rl0 = r0 + g, rl1 = rl0 + 8;
    #pragma unroll
    for (int nt = 0; nt < 12; ++nt) {
        int col = nt*8 + 2*tig;
        float b0v = bf[col], b1v = bf[col+1];
        float2 in0 = *reinterpret_cast<const float2*>(input + (size_t)gr0*96 + col);
        float2 in1 = *reinterpret_cast<const float2*>(input + (size_t)gr1*96 + col);
        float z00 = 1.f/(1.f+expf(-(acc[nt][0] + b0v)));
        float z01 = 1.f/(1.f+expf(-(acc[nt][1] + b1v)));
        float z10 = 1.f/(1.f+expf(-(acc[nt][2] + b0v)));
        float z11 = 1.f/(1.f+expf(-(acc[nt][3] + b1v)));
        float sp00 = Xsp[rl0*100 + col], sp01 = Xsp[rl0*100 + col + 1];
        float sp10 = Xsp[rl1*100 + col], sp11 = Xsp[rl1*100 + col + 1];
        float tp00 = Xtp[rl0*100 + col], tp01 = Xtp[rl0*100 + col + 1];
        float tp10 = Xtp[rl1*100 + col], tp11 = Xtp[rl1*100 + col + 1];
        float2 o0 = make_float2(z00*sp00 + (1.f-z00)*tp00 + in0.x,
                                z01*sp01 + (1.f-z01)*tp01 + in0.y);
        float2 o1 = make_float2(z10*sp10 + (1.f-z10)*tp10 + in1.x,
                                z11*sp11 + (1.f-z11)*tp11 + in1.y);
        *reinterpret_cast<float2*>(outp + (size_t)gr0*96 + col) = o0;
        *reinterpret_cast<float2*>(outp + (size_t)gr1*96 + col) = o1;
    }
}

extern "C" void kernel_launch(void* const* d_in, const int* in_sizes, int n_in,
                              void* d_out, int out_size)
{
    const float* input = (const float*)d_in[0];
    const float* spatE = (const float*)d_in[1];
    const float* tempE = (const float*)d_in[2];
    const int*   s0 = (const int*)d_in[3];
    const int*   s1 = (const int*)d_in[5];
    const int*   s2 = (const int*)d_in[7];
    const float* W_d = (const float*)d_in[9];
    const float* al_d = (const float*)d_in[10];
    const float* ar_d = (const float*)d_in[11];
    const float* b_d = (const float*)d_in[12];
    const float* W_m = (const float*)d_in[13];
    const float* al_m = (const float*)d_in[14];
    const float* ar_m = (const float*)d_in[15];
    const float* b_m = (const float*)d_in[16];
    const float* W_s = (const float*)d_in[17];
    const float* al_s = (const float*)d_in[18];
    const float* ar_s = (const float*)d_in[19];
    const float* b_s = (const float*)d_in[20];
    const float* Wg  = (const float*)d_in[21];
    const float* agl = (const float*)d_in[22];
    const float* agr = (const float*)d_in[23];
    const float* Wf  = (const float*)d_in[24];
    const float* bf  = (const float*)d_in[25];
    float* out   = (float*)d_out;
    float* attnS = out + (size_t)RR*96;   // out (B,T,N,F) then attn_S (B,N,N)

    const int SP_SMEM  = (128*100 + 3*96*104) * 4;         // 171,008 B
    const int TP_SMEM  = (128*100 + 96*104) * 4;           //  91,136 B
    const int FUS_SMEM = (2*128*100 + 192*104) * 4;        // 182,272 B
    const int ATS_SMEM = (2*64*97) * 4;                    //  49,664 B

    static cudaStream_t stB = 0, stC = 0;
    static cudaEvent_t evFork = 0, evB = 0, evC = 0;
    static int inited = 0;
    static int use_streams = 0;
    if (!inited) {
        cudaFuncSetAttribute(gemm_tc_sp, cudaFuncAttributeMaxDynamicSharedMemorySize, SP_SMEM);
        cudaFuncSetAttribute(gemm_tc_tp, cudaFuncAttributeMaxDynamicSharedMemorySize, TP_SMEM);
        cudaFuncSetAttribute(fusion_tc,  cudaFuncAttributeMaxDynamicSharedMemorySize, FUS_SMEM);
        cudaFuncSetAttribute(attnS_gemm, cudaFuncAttributeMaxDynamicSharedMemorySize, ATS_SMEM);
        use_streams = 1;
        if (cudaStreamCreateWithFlags(&stB, cudaStreamNonBlocking) != cudaSuccess) use_streams = 0;
        if (use_streams && cudaStreamCreateWithFlags(&stC, cudaStreamNonBlocking) != cudaSuccess) use_streams = 0;
        if (use_streams && cudaEventCreateWithFlags(&evFork, cudaEventDisableTiming) != cudaSuccess) use_streams = 0;
        if (use_streams && cudaEventCreateWithFlags(&evB,    cudaEventDisableTiming) != cudaSuccess) use_streams = 0;
        if (use_streams && cudaEventCreateWithFlags(&evC,    cudaEventDisableTiming) != cudaSuccess) use_streams = 0;
        inited = 1;
    }

    if (use_streams) {
        cudaStreamCaptureMode mode = cudaStreamCaptureModeRelaxed;
        cudaThreadExchangeStreamCaptureMode(&mode);

        cudaEventRecord(evFork, 0);
        cudaStreamWaitEvent(stB, evFork, 0);
        cudaStreamWaitEvent(stC, evFork, 0);

        // chain A first (critical path): spatial GEMM (3 gats) -> aggregation
        gemm_tc_sp<<<RGRID, 256, SP_SMEM>>>(input, spatE,
            W_d, W_m, W_s, al_d, al_m, al_s, ar_d, ar_m, ar_s);
        gat_agg3<<<dim3(NN, 3), 256>>>(s0, s1, s2, b_d, b_m, b_s, input);

        // chain B: attn_T FIRST (no deps, hides its latency), then projection,
        // then the temporal branch.
        attnT_kernel<<<4, dim3(24,24), 0, stB>>>(tempE);
        gemm_tc_tp<<<RGRID, 256, TP_SMEM, stB>>>(input, Wg, agl, agr);
        temporal2<<<4096, 288, 0, stB>>>(input);
        cudaEventRecord(evB, stB);

        // chain C: attn_S output (independent)
        attnS_gemm<<<dim3(16,16,4), 256, ATS_SMEM, stC>>>(spatE, attnS);
        rowsoftmax1024<<<4096, 256, 0, stC>>>(attnS);
        cudaEventRecord(evC, stC);

        cudaStreamWaitEvent(0, evB, 0);
        fusion_tc<<<RGRID, 256, FUS_SMEM>>>(input, Wf, bf, out);
        cudaStreamWaitEvent(0, evC, 0);

        cudaThreadExchangeStreamCaptureMode(&mode);   // restore
    } else {
        // sequential fallback
        gemm_tc_sp<<<RGRID, 256, SP_SMEM>>>(input, spatE,
            W_d, W_m, W_s, al_d, al_m, al_s, ar_d, ar_m, ar_s);
        gemm_tc_tp<<<RGRID, 256, TP_SMEM>>>(input, Wg, agl, agr);
        gat_agg3<<<dim3(NN, 3), 256>>>(s0, s1, s2, b_d, b_m, b_s, input);
        attnS_gemm<<<dim3(16,16,4), 256, ATS_SMEM>>>(spatE, attnS);
        rowsoftmax1024<<<4096, 256>>>(attnS);
        attnT_kernel<<<4, dim3(24,24)>>>(tempE);
        temporal2<<<4096, 288>>>(input);
        fusion_tc<<<RGRID, 256, FUS_SMEM>>>(input, Wf, bf, out);
    }
}

// round 15
// speedup vs baseline: 1.1723x; 1.0937x over previous
#include <cuda_runtime.h>
#include <cuda_fp16.h>
#include <math.h>
#include <stdint.h>

#define NN 1024
#define BB 4
#define TT 24
#define FF 96
#define RR (NN*96)       // 98304 rows (== B*T*N)
#define RGRID (RR/128)   // 768
#define SPGRID (RR/256)  // 384

// ---------------- scratch (device globals; no allocs allowed) ----------------
__device__ __half g_h3[3*(size_t)RR*96];  // spatial GAT h (fp16), per gat
__device__ float g_el3[3*RR*3];
__device__ float g_er3[3*RR*3];
__device__ float g_hg[(size_t)RR*96];     // temporal hg (fp32), row = (b*N+n)*24+t
__device__ float g_elg[RR*4];
__device__ float g_erg[RR*4];
__device__ float g_spatial[(size_t)RR*96];
__device__ float g_temporal[(size_t)RR*96];
__device__ float g_attnT[BB*TT*TT];

// ---------------- tf32 helpers ----------------
__device__ __forceinline__ uint32_t f2tf32(float x) {
    uint32_t r; asm("cvt.rna.tf32.f32 %0, %1;" : "=r"(r) : "f"(x)); return r;
}
__device__ __forceinline__ void mma_tf32(float* c, const uint32_t* a, uint32_t b0, uint32_t b1) {
    asm volatile("mma.sync.aligned.m16n8k8.row.col.f32.tf32.tf32.f32 "
        "{%0,%1,%2,%3}, {%4,%5,%6,%7}, {%8,%9}, {%0,%1,%2,%3};"
        : "+f"(c[0]), "+f"(c[1]), "+f"(c[2]), "+f"(c[3])
        : "r"(a[0]), "r"(a[1]), "r"(a[2]), "r"(a[3]), "r"(b0), "r"(b1));
}

// ======= spatial GEMM v2: 256 rows x 96 cols, 512 threads, ALL 3 GATs ========
// 16 warps -> 2x the latency hiding of the 128-row version at 1 CTA/SM.
__global__ __launch_bounds__(512)
void gemm_tc_sp(const float* __restrict__ X, const float* __restrict__ Emb,
                const float* __restrict__ W0, const float* __restrict__ W1, const float* __restrict__ W2,
                const float* __restrict__ al0, const float* __restrict__ al1, const float* __restrict__ al2,
                const float* __restrict__ ar0, const float* __restrict__ ar1, const float* __restrict__ ar2)
{
    extern __shared__ float sm[];
    float*    Xs = sm;                                 // [256][100] fp32
    uint32_t* Ws = (uint32_t*)(sm + 256*100);          // 3 x [96][104] tf32

    const int tid = threadIdx.x;                       // 512
    const int row0 = blockIdx.x * 256;
    const float* Wp[3]  = {W0, W1, W2};
    const float* alp[3] = {al0, al1, al2};
    const float* arp[3] = {ar0, ar1, ar2};

    for (int i = tid; i < 3*2304; i += 512) {
        int gat = i / 2304, rem = i % 2304;
        int k = rem / 24, c4 = rem % 24;
        float4 v = reinterpret_cast<const float4*>(Wp[gat])[rem];
        *reinterpret_cast<uint4*>(&Ws[gat*96*104 + k*104 + c4*4]) =
            make_uint4(f2tf32(v.x), f2tf32(v.y), f2tf32(v.z), f2tf32(v.w));
    }
    for (int i = tid; i < 6144; i += 512) {
        int r = i / 24, c4 = i % 24;
        int gr = row0 + r;
        int n = gr / 96, k = gr % 96;
        int b = k & 3, t = k >> 2;
        int off = ((b*TT + t)*NN + n)*FF;
        float4 v = *reinterpret_cast<const float4*>(X + off + c4*4);
        float4 e = *reinterpret_cast<const float4*>(Emb + off + c4*4);
        v.x += e.x; v.y += e.y; v.z += e.z; v.w += e.w;
        *reinterpret_cast<float4*>(&Xs[r*100 + c4*4]) = v;
    }
    __syncthreads();

    const int lane = tid & 31, w = tid >> 5;           // w 0..15
    const int g = lane >> 2, tig = lane & 3;
    const int r0 = w * 16;
    const int gr0 = row0 + r0 + g, gr1 = gr0 + 8;

    uint32_t af[12][4];
    #pragma unroll
    for (int ks = 0; ks < 12; ++ks) {
        int k0 = ks * 8;
        af[ks][0] = f2tf32(Xs[(r0+g  )*100 + k0 + tig    ]);
        af[ks][1] = f2tf32(Xs[(r0+g+8)*100 + k0 + tig    ]);
        af[ks][2] = f2tf32(Xs[(r0+g  )*100 + k0 + tig + 4]);
        af[ks][3] = f2tf32(Xs[(r0+g+8)*100 + k0 + tig + 4]);
    }

    for (int gat = 0; gat < 3; ++gat) {
        const uint32_t* Wg_ = Ws + gat*96*104;
        float acc[12][4];
        #pragma unroll
        for (int nt = 0; nt < 12; ++nt)
            #pragma unroll
            for (int q = 0; q < 4; ++q) acc[nt][q] = 0.f;
        #pragma unroll
        for (int ks = 0; ks < 12; ++ks) {
            int k0 = ks * 8;
            #pragma unroll
            for (int nt = 0; nt < 12; ++nt) {
                uint32_t b0 = Wg_[(k0+tig  )*104 + nt*8 + g];
                uint32_t b1 = Wg_[(k0+tig+4)*104 + nt*8 + g];
                mma_tf32(acc[nt], af[ks], b0, b1);
            }
        }
        __half* Hb = g_h3 + (size_t)gat*RR*96;
        #pragma unroll
        for (int nt = 0; nt < 12; ++nt) {
            *reinterpret_cast<__half2*>(Hb + (size_t)gr0*96 + nt*8 + 2*tig) =
                __floats2half2_rn(acc[nt][0], acc[nt][1]);
            *reinterpret_cast<__half2*>(Hb + (size_t)gr1*96 + nt*8 + 2*tig) =
                __floats2half2_rn(acc[nt][2], acc[nt][3]);
        }
        const float* al = alp[gat];
        const float* ar = arp[gat];
        #pragma unroll
        for (int h = 0; h < 3; ++h) {
            float sl0 = 0.f, sr0 = 0.f, sl1 = 0.f, sr1 = 0.f;
            #pragma unroll
            for (int q = 0; q < 4; ++q) {
                int nt = h*4 + q;
                float a0 = al[nt*8 + 2*tig], a1 = al[nt*8 + 2*tig + 1];
                float c0 = ar[nt*8 + 2*tig], c1 = ar[nt*8 + 2*tig + 1];
                sl0 += acc[nt][0]*a0 + acc[nt][1]*a1;
                sr0 += acc[nt][0]*c0 + acc[nt][1]*c1;
                sl1 += acc[nt][2]*a0 + acc[nt][3]*a1;
                sr1 += acc[nt][2]*c0 + acc[nt][3]*c1;
            }
            sl0 += __shfl_xor_sync(0xffffffffu, sl0, 1); sl0 += __shfl_xor_sync(0xffffffffu, sl0, 2);
            sr0 += __shfl_xor_sync(0xffffffffu, sr0, 1); sr0 += __shfl_xor_sync(0xffffffffu, sr0, 2);
            sl1 += __shfl_xor_sync(0xffffffffu, sl1, 1); sl1 += __shfl_xor_sync(0xffffffffu, sl1, 2);
            sr1 += __shfl_xor_sync(0xffffffffu, sr1, 1); sr1 += __shfl_xor_sync(0xffffffffu, sr1, 2);
            if (tig == 0) {
                g_el3[(size_t)gat*RR*3 + gr0*3 + h] = sl0;
                g_er3[(size_t)gat*RR*3 + gr0*3 + h] = sr0;
                g_el3[(size_t)gat*RR*3 + gr1*3 + h] = sl1;
                g_er3[(size_t)gat*RR*3 + gr1*3 + h] = sr1;
            }
        }
    }
}

// ======= temporal projection GEMM v2: BTN-ordered rows (coalesced X reads) ===
// Block processes 128 consecutive input-linear rows ir = (b*24+t)*1024+n:
// X load is one contiguous 48KB span. Output rows ro = ((b*N+n)*24+t) are
// scattered, but stores don't stall.
__global__ __launch_bounds__(256)
void gemm_tc_tp(const float* __restrict__ X, const float* __restrict__ W,
                const float* __restrict__ al, const float* __restrict__ ar)
{
    extern __shared__ float sm[];
    float*    Xs = sm;                                 // [128][100]
    uint32_t* Ws = (uint32_t*)(sm + 128*100);          // [96][104]
    const int tid = threadIdx.x;
    const int row0 = blockIdx.x * 128;                 // input-linear row base

    for (int i = tid; i < 2304; i += 256) {
        int k = i / 24, c4 = i % 24;
        float4 v = reinterpret_cast<const float4*>(W)[i];
        *reinterpret_cast<uint4*>(&Ws[k*104 + c4*4]) =
            make_uint4(f2tf32(v.x), f2tf32(v.y), f2tf32(v.z), f2tf32(v.w));
    }
    for (int i = tid; i < 3072; i += 256) {
        int r = i / 24, c4 = i % 24;
        *reinterpret_cast<float4*>(&Xs[r*100 + c4*4]) =
            *reinterpret_cast<const float4*>(X + (size_t)(row0 + r)*96 + c4*4);
    }
    __syncthreads();

    const int lane = tid & 31, w = tid >> 5;
    const int g = lane >> 2, tig = lane & 3;
    const int r0 = w * 16;
    float acc[12][4];
    #pragma unroll
    for (int nt = 0; nt < 12; ++nt)
        #pragma unroll
        for (int q = 0; q < 4; ++q) acc[nt][q] = 0.f;
    #pragma unroll
    for (int ks = 0; ks < 12; ++ks) {
        int k0 = ks * 8;
        uint32_t a[4];
        a[0] = f2tf32(Xs[(r0+g  )*100 + k0 + tig    ]);
        a[1] = f2tf32(Xs[(r0+g+8)*100 + k0 + tig    ]);
        a[2] = f2tf32(Xs[(r0+g  )*100 + k0 + tig + 4]);
        a[3] = f2tf32(Xs[(r0+g+8)*100 + k0 + tig + 4]);
        #pragma unroll
        for (int nt = 0; nt < 12; ++nt) {
            uint32_t b0 = Ws[(k0+tig  )*104 + nt*8 + g];
            uint32_t b1 = Ws[(k0+tig+4)*104 + nt*8 + g];
            mma_tf32(acc[nt], a, b0, b1);
        }
    }
    // map input-linear rows -> (b*N+n)*24+t output rows
    const int ir0 = row0 + r0 + g, ir1 = ir0 + 8;
    const int n0 = ir0 & 1023, bt0 = ir0 >> 10;
    const int n1 = ir1 & 1023, bt1 = ir1 >> 10;
    const int b0r = bt0 / 24, t0r = bt0 % 24;
    const int b1r = bt1 / 24, t1r = bt1 % 24;
    const int ro0 = ((b0r*NN + n0)*TT + t0r);
    const int ro1 = ((b1r*NN + n1)*TT + t1r);
    #pragma unroll
    for (int nt = 0; nt < 12; ++nt) {
        *reinterpret_cast<float2*>(g_hg + (size_t)ro0*96 + nt*8 + 2*tig) = make_float2(acc[nt][0], acc[nt][1]);
        *reinterpret_cast<float2*>(g_hg + (size_t)ro1*96 + nt*8 + 2*tig) = make_float2(acc[nt][2], acc[nt][3]);
    }
    #pragma unroll
    for (int h = 0; h < 4; ++h) {
        float sl0 = 0.f, sr0 = 0.f, sl1 = 0.f, sr1 = 0.f;
        #pragma unroll
        for (int q = 0; q < 3; ++q) {
            int nt = h*3 + q;
            float a0 = al[nt*8 + 2*tig], a1 = al[nt*8 + 2*tig + 1];
            float c0 = ar[nt*8 + 2*tig], c1 = ar[nt*8 + 2*tig + 1];
            sl0 += acc[nt][0]*a0 + acc[nt][1]*a1;
            sr0 += acc[nt][0]*c0 + acc[nt][1]*c1;
            sl1 += acc[nt][2]*a0 + acc[nt][3]*a1;
            sr1 += acc[nt][2]*c0 + acc[nt][3]*c1;
        }
        sl0 += __shfl_xor_sync(0xffffffffu, sl0, 1); sl0 += __shfl_xor_sync(0xffffffffu, sl0, 2);
        sr0 += __shfl_xor_sync(0xffffffffu, sr0, 1); sr0 += __shfl_xor_sync(0xffffffffu, sr0, 2);
        sl1 += __shfl_xor_sync(0xffffffffu, sl1, 1); sl1 += __shfl_xor_sync(0xffffffffu, sl1, 2);
        sr1 += __shfl_xor_sync(0xffffffffu, sr1, 1); sr1 += __shfl_xor_sync(0xffffffffu, sr1, 2);
        if (tig == 0) {
            g_elg[ro0*4 + h] = sl0;  g_erg[ro0*4 + h] = sr0;
            g_elg[ro1*4 + h] = sl1;  g_erg[ro1*4 + h] = sr1;
        }
    }
}

// -------- GAT aggregation v3: half2 gather, thread = (dd 0..15, kg 0..15) ----
__global__ __launch_bounds__(256)
void gat_agg3(const int* __restrict__ src0, const int* __restrict__ src1,
              const int* __restrict__ src2,
              const float* __restrict__ bias0, const float* __restrict__ bias1,
              const float* __restrict__ bias2,
              const float* __restrict__ inp)
{
    const int gat = blockIdx.y, n = blockIdx.x, tid = threadIdx.x;
    const int*   src  = (gat == 0) ? src0  : (gat == 1) ? src1  : src2;
    const float* bias = (gat == 0) ? bias0 : (gat == 1) ? bias1 : bias2;
    const __half* H  = g_h3  + (size_t)gat*RR*96;
    const float* EL = g_el3 + (size_t)gat*RR*3;
    const float* ER = g_er3 + (size_t)gat*RR*3;

    __shared__ int   ssm[8];
    __shared__ float er_s[288];
    __shared__ float as[2304];      // [q = k*3+h][j]
    __shared__ float bsum[32];

    if (tid < 8)  ssm[tid] = src[n + tid*NN];
    if (tid < 32) bsum[tid] = bias[tid] + bias[32 + tid] + bias[64 + tid];
    for (int q = tid; q < 288; q += 256) er_s[q] = ER[n*288 + q];
    __syncthreads();

    for (int j = 0; j < 8; ++j) {
        const float* elp = EL + (size_t)ssm[j] * 288;
        for (int q = tid; q < 288; q += 256) {
            float x = elp[q] + er_s[q];
            as[q*8 + j] = (x >= 0.f) ? x : 0.2f*x;
        }
    }
    __syncthreads();
    for (int q = tid; q < 288; q += 256) {
        float e[8], m = -1e30f;
        #pragma unroll
        for (int j = 0; j < 8; ++j) { e[j] = as[q*8 + j]; m = fmaxf(m, e[j]); }
        float s = 0.f;
        #pragma unroll
        for (int j = 0; j < 8; ++j) { e[j] = expf(e[j] - m); s += e[j]; }
        float inv = 1.f / (s + 1e-9f);
        #pragma unroll
        for (int j = 0; j < 8; ++j) as[q*8 + j] = e[j] * inv;
    }
    __syncthreads();

    const int dd = tid & 15, kg = tid >> 4;
    float2 acc[6];
    #pragma unroll
    for (int s = 0; s < 6; ++s) acc[s] = make_float2(0.f, 0.f);
    for (int j = 0; j < 8; ++j) {
        const __half2* hb2 = reinterpret_cast<const __half2*>(H + (size_t)ssm[j] * 96 * 96);
        #pragma unroll
        for (int s = 0; s < 6; ++s) {
            int k = kg + 16*s;
            const __half2* hp2 = hb2 + k*48;
            float a0 = as[(k*3+0)*8 + j];
            float a1 = as[(k*3+1)*8 + j];
            float a2 = as[(k*3+2)*8 + j];
            float2 h0 = __half22float2(hp2[dd]);
            float2 h1 = __half22float2(hp2[16 + dd]);
            float2 h2 = __half22float2(hp2[32 + dd]);
            acc[s].x += a0*h0.x + a1*h1.x + a2*h2.x;
            acc[s].y += a0*h0.y + a1*h1.y + a2*h2.y;
        }
    }
    float b0v = bsum[2*dd], b1v = bsum[2*dd + 1];
    #pragma unroll
    for (int s = 0; s < 6; ++s) {
        int k = kg + 16*s;
        float vx = (acc[s].x + b0v) * (1.f/3.f);
        float vy = (acc[s].y + b1v) * (1.f/3.f);
        int ob = k / 24, ot = k % 24;      // reference's reshape scramble
        size_t o = (size_t)((ob*TT + ot)*NN + n)*FF + gat*32 + 2*dd;
        float2 iv = *reinterpret_cast<const float2*>(inp + o);
        *reinterpret_cast<float2*>(g_spatial + o) = make_float2(iv.x + vx, iv.y + vy);
    }
}

// ---------------- attn_S = softmax(cov0 @ cov0^T, axis=2) -- fp32 ------------
__global__ __launch_bounds__(256)
void attnS_gemm(const float* __restrict__ spatE, float* __restrict__ Sout)
{
    extern __shared__ float sm2[];
    float* At = sm2;            // [64][97]
    float* Bt = sm2 + 64*97;    // [64][97]
    int b = blockIdx.z;
    int i0 = blockIdx.y * 64, j0 = blockIdx.x * 64;
    const float* cov = spatE + (size_t)b*TT*NN*FF;   // t = 0 slice
    int tid = threadIdx.x;       // 256
    #pragma unroll
    for (int i = 0; i < 6; ++i) {
        int idx = tid + i*256;   // < 1536
        int r = idx / 24, c4 = idx % 24;
        float4 v = *reinterpret_cast<const float4*>(cov + (i0 + r)*96 + c4*4);
        At[r*97 + c4*4+0] = v.x; At[r*97 + c4*4+1] = v.y;
        At[r*97 + c4*4+2] = v.z; At[r*97 + c4*4+3] = v.w;
        float4 w = *reinterpret_cast<const float4*>(cov + (j0 + r)*96 + c4*4);
        Bt[r*97 + c4*4+0] = w.x; Bt[r*97 + c4*4+1] = w.y;
        Bt[r*97 + c4*4+2] = w.z; Bt[r*97 + c4*4+3] = w.w;
    }
    __syncthreads();
    int tx = tid & 15, ty = tid >> 4;
    float acc[4][4];
    #pragma unroll
    for (int u = 0; u < 4; ++u)
        #pragma unroll
        for (int v = 0; v < 4; ++v) acc[u][v] = 0.f;
    #pragma unroll 8
    for (int f = 0; f < 96; ++f) {
        float a[4], bb[4];
        #pragma unroll
        for (int u = 0; u < 4; ++u) a[u] = At[(ty*4+u)*97 + f];
        #pragma unroll
        for (int v = 0; v < 4; ++v) bb[v] = Bt[(tx*4+v)*97 + f];
        #pragma unroll
        for (int u = 0; u < 4; ++u)
            #pragma unroll
            for (int v = 0; v < 4; ++v) acc[u][v] = fmaf(a[u], bb[v], acc[u][v]);
    }
    #pragma unroll
    for (int u = 0; u < 4; ++u) {
        float4 o = make_float4(acc[u][0], acc[u][1], acc[u][2], acc[u][3]);
        *reinterpret_cast<float4*>(Sout + ((size_t)b*NN + i0 + ty*4 + u)*NN + j0 + tx*4) = o;
    }
}

__global__ void rowsoftmax1024(float* __restrict__ S)
{
    int row = blockIdx.x;
    float* p = S + (size_t)row * 1024;
    int tid = threadIdx.x;   // 256
    float v[4];
    float m = -1e30f;
    #pragma unroll
    for (int q = 0; q < 4; ++q) { v[q] = p[tid + q*256]; m = fmaxf(m, v[q]); }
    __shared__ float red[8];
    __shared__ float red2[8];
    for (int o = 16; o >= 1; o >>= 1) m = fmaxf(m, __shfl_xor_sync(0xffffffffu, m, o));
    if ((tid & 31) == 0) red[tid >> 5] = m;
    __syncthreads();
    float mm = red[0];
    #pragma unroll
    for (int w = 1; w < 8; ++w) mm = fmaxf(mm, red[w]);
    float s = 0.f;
    #pragma unroll
    for (int q = 0; q < 4; ++q) { v[q] = expf(v[q] - mm); s += v[q]; }
    for (int o = 16; o >= 1; o >>= 1) s += __shfl_xor_sync(0xffffffffu, s, o);
    if ((tid & 31) == 0) red2[tid >> 5] = s;
    __syncthreads();
    float ss = 0.f;
    #pragma unroll
    for (int w = 0; w < 8; ++w) ss += red2[w];
    float inv = 1.f / ss;
    #pragma unroll
    for (int q = 0; q < 4; ++q) p[tid + q*256] = v[q] * inv;
}

// ---------------- attn_T = softmax(covT @ covT^T, axis=1) --------------------
__global__ void attnT_kernel(const float* __restrict__ tempE)
{
    __shared__ float cov[24][96];
    __shared__ float s[24][25];
    __shared__ float colmax[24], colsum[24];
    int b = blockIdx.x;
    int j = threadIdx.x, i = threadIdx.y;
    int tid = i*24 + j;
    for (int q = tid; q < 2304; q += 576) {
        int t = q / 96, f = q % 96;
        cov[t][f] = tempE[((b*TT + t)*NN)*FF + f];   // n = 0 slice
    }
    __syncthreads();
    float acc = 0.f;
    #pragma unroll
    for (int f = 0; f < 96; ++f) acc = fmaf(cov[i][f], cov[j][f], acc);
    s[i][j] = acc;
    __syncthreads();
    if (i == 0) {
        float m = -1e30f;
        for (int t = 0; t < 24; ++t) m = fmaxf(m, s[t][j]);
        colmax[j] = m;
    }
    __syncthreads();
    float e = expf(acc - colmax[j]);
    s[i][j] = e;
    __syncthreads();
    if (i == 0) {
        float sm0 = 0.f;
        for (int t = 0; t < 24; ++t) sm0 += s[t][j];
        colsum[j] = sm0;
    }
    __syncthreads();
    g_attnT[(b*TT + i)*TT + j] = e / colsum[j];
}

// ---------------- temporal branch v2: 288 threads, register-hoisted ----------
__global__ __launch_bounds__(288)
void temporal2(const float* __restrict__ input)
{
    __shared__ float hgs[2304];
    __shared__ float xts[2304];
    __shared__ float alph[2304];
    __shared__ float ats[576];
    __shared__ float elgs[96], ergs[96];
    int r = blockIdx.x;              // r = b*N + n
    int b = r >> 10, n = r & 1023;
    int tid = threadIdx.x;           // 288
    for (int q = tid; q < 2304; q += 288) hgs[q] = g_hg[(size_t)r*2304 + q];
    for (int q = tid; q < 2304; q += 288) {
        int t = q / 96, f = q % 96;
        xts[q] = input[((b*TT + t)*NN + n)*FF + f];
    }
    if (tid < 96) { elgs[tid] = g_elg[r*96 + tid]; ergs[tid] = g_erg[r*96 + tid]; }
    for (int q = tid; q < 576; q += 288) ats[q] = g_attnT[(n & 3)*576 + q]; // idx = r%B = n%4
    __syncthreads();
    if (tid < 96) {                  // softmax over j for (i,g)
        int i = tid >> 2, g = tid & 3;
        float eli = elgs[i*4 + g];
        float ev[24];
        float m = -1e30f;
        #pragma unroll
        for (int j = 0; j < 24; ++j) {
            float x = eli + ergs[j*4 + g];
            x = (x >= 0.f) ? x : 0.2f*x;
            ev[j] = x;
            m = fmaxf(m, x);
        }
        float s = 0.f;
        #pragma unroll
        for (int j = 0; j < 24; ++j) { ev[j] = expf(ev[j] - m); s += ev[j]; }
        float inv = 1.f / s;
        #pragma unroll
        for (int j = 0; j < 24; ++j) alph[tid*24 + j] = ev[j]*inv;
    }
    __syncthreads();

    int f = tid % 96, tr = tid / 96;       // tr 0..2
    int g = f / 24;
    float hv[24], xv[24];
    #pragma unroll
    for (int j = 0; j < 24; ++j) { hv[j] = hgs[j*96 + f]; xv[j] = xts[j*96 + f]; }
    #pragma unroll
    for (int s = 0; s < 8; ++s) {
        int i = tr + 3*s;
        float xa = 0.f, ea = 0.f;
        const float* ap = &alph[(i*4 + g)*24];
        const float* tp = &ats[i*24];
        #pragma unroll
        for (int j = 0; j < 24; ++j) {
            xa = fmaf(ap[j], hv[j], xa);
            ea = fmaf(tp[j], xv[j], ea);
        }
        float sg = 1.f / (1.f + expf(-ea));
        g_temporal[(size_t)((b*TT + i)*NN + n)*FF + f] = xv[i] + xa*sg;
    }
}

// ---------------- fusion (tensor-core): z = sigmoid([sp,tp]@Wf + bf) ---------
__global__ __launch_bounds__(256)
void fusion_tc(const float* __restrict__ input, const float* __restrict__ Wf,
               const float* __restrict__ bf, float* __restrict__ outp)
{
    extern __shared__ float sm[];
    float*    Xsp = sm;                                  // [128][100] fp32
    float*    Xtp = sm + 128*100;                        // [128][100] fp32
    uint32_t* Ws  = (uint32_t*)(sm + 2*128*100);         // [192][104] tf32

    const int tid = threadIdx.x;
    const int row0 = blockIdx.x * 128;

    for (int i = tid; i < 192*24; i += 256) {
        int k = i / 24, c4 = i % 24;
        float4 v = reinterpret_cast<const float4*>(Wf)[i];
        *reinterpret_cast<uint4*>(&Ws[k*104 + c4*4]) =
            make_uint4(f2tf32(v.x), f2tf32(v.y), f2tf32(v.z), f2tf32(v.w));
    }
    for (int i = tid; i < 3072; i += 256) {
        int r = i / 24, c4 = i % 24;
        size_t off = (size_t)(row0 + r)*96 + c4*4;
        *reinterpret_cast<float4*>(&Xsp[r*100 + c4*4]) = *reinterpret_cast<const float4*>(g_spatial + off);
        *reinterpret_cast<float4*>(&Xtp[r*100 + c4*4]) = *reinterpret_cast<const float4*>(g_temporal + off);
    }
    __syncthreads();

    const int lane = tid & 31, w = tid >> 5;
    const int g = lane >> 2, tig = lane & 3;
    const int r0 = w * 16;

    float acc[12][4];
    #pragma unroll
    for (int nt = 0; nt < 12; ++nt)
        #pragma unroll
        for (int q = 0; q < 4; ++q) acc[nt][q] = 0.f;

    #pragma unroll
    for (int ks = 0; ks < 12; ++ks) {           // spatial half (Wf rows 0..95)
        int k0 = ks * 8;
        uint32_t a[4];
        a[0] = f2tf32(Xsp[(r0+g  )*100 + k0 + tig    ]);
        a[1] = f2tf32(Xsp[(r0+g+8)*100 + k0 + tig    ]);
        a[2] = f2tf32(Xsp[(r0+g  )*100 + k0 + tig + 4]);
        a[3] = f2tf32(Xsp[(r0+g+8)*100 + k0 + tig + 4]);
        #pragma unroll
        for (int nt = 0; nt < 12; ++nt) {
            uint32_t b0 = Ws[(k0+tig  )*104 + nt*8 + g];
            uint32_t b1 = Ws[(k0+tig+4)*104 + nt*8 + g];
            mma_tf32(acc[nt], a, b0, b1);
        }
    }
    #pragma unroll
    for (int ks = 0; ks < 12; ++ks) {           // temporal half (Wf rows 96..191)
        int k0 = ks * 8;
        uint32_t a[4];
        a[0] = f2tf32(Xtp[(r0+g  )*100 + k0 + tig    ]);
        a[1] = f2tf32(Xtp[(r0+g+8)*100 + k0 + tig    ]);
        a[2] = f2tf32(Xtp[(r0+g  )*100 + k0 + tig + 4]);
        a[3] = f2tf32(Xtp[(r0+g+8)*100 + k0 + tig + 4]);
        #pragma unroll
        for (int nt = 0; nt < 12; ++nt) {
            uint32_t b0 = Ws[(96+k0+tig  )*104 + nt*8 + g];
            uint32_t b1 = Ws[(96+k0+tig+4)*104 + nt*8 + g];
            mma_tf32(acc[nt], a, b0, b1);
        }
    }

    const int gr0 = row0 + r0 + g, gr1 = gr0 + 8;
    const int rl0 = r0 + g, rl1 = rl0 + 8;
    #pragma unroll
    for (int nt = 0; nt < 12; ++nt) {
        int col = nt*8 + 2*tig;
        float b0v = bf[col], b1v = bf[col+1];
        float2 in0 = *reinterpret_cast<const float2*>(input + (size_t)gr0*96 + col);
        float2 in1 = *reinterpret_cast<const float2*>(input + (size_t)gr1*96 + col);
        float z00 = 1.f/(1.f+expf(-(acc[nt][0] + b0v)));
        float z01 = 1.f/(1.f+expf(-(acc[nt][1] + b1v)));
        float z10 = 1.f/(1.f+expf(-(acc[nt][2] + b0v)));
        float z11 = 1.f/(1.f+expf(-(acc[nt][3] + b1v)));
        float sp00 = Xsp[rl0*100 + col], sp01 = Xsp[rl0*100 + col + 1];
        float sp10 = Xsp[rl1*100 + col], sp11 = Xsp[rl1*100 + col + 1];
        float tp00 = Xtp[rl0*100 + col], tp01 = Xtp[rl0*100 + col + 1];
        float tp10 = Xtp[rl1*100 + col], tp11 = Xtp[rl1*100 + col + 1];
        float2 o0 = make_float2(z00*sp00 + (1.f-z00)*tp00 + in0.x,
                                z01*sp01 + (1.f-z01)*tp01 + in0.y);
        float2 o1 = make_float2(z10*sp10 + (1.f-z10)*tp10 + in1.x,
                                z11*sp11 + (1.f-z11)*tp11 + in1.y);
        *reinterpret_cast<float2*>(outp + (size_t)gr0*96 + col) = o0;
        *reinterpret_cast<float2*>(outp + (size_t)gr1*96 + col) = o1;
    }
}

extern "C" void kernel_launch(void* const* d_in, const int* in_sizes, int n_in,
                              void* d_out, int out_size)
{
    const float* input = (const float*)d_in[0];
    const float* spatE = (const float*)d_in[1];
    const float* tempE = (const float*)d_in[2];
    const int*   s0 = (const int*)d_in[3];
    const int*   s1 = (const int*)d_in[5];
    const int*   s2 = (const int*)d_in[7];
    const float* W_d = (const float*)d_in[9];
    const float* al_d = (const float*)d_in[10];
    const float* ar_d = (const float*)d_in[11];
    const float* b_d = (const float*)d_in[12];
    const float* W_m = (const float*)d_in[13];
    const float* al_m = (const float*)d_in[14];
    const float* ar_m = (const float*)d_in[15];
    const float* b_m = (const float*)d_in[16];
    const float* W_s = (const float*)d_in[17];
    const float* al_s = (const float*)d_in[18];
    const float* ar_s = (const float*)d_in[19];
    const float* b_s = (const float*)d_in[20];
    const float* Wg  = (const float*)d_in[21];
    const float* agl = (const float*)d_in[22];
    const float* agr = (const float*)d_in[23];
    const float* Wf  = (const float*)d_in[24];
    const float* bf  = (const float*)d_in[25];
    float* out   = (float*)d_out;
    float* attnS = out + (size_t)RR*96;   // out (B,T,N,F) then attn_S (B,N,N)

    const int SP_SMEM  = (256*100 + 3*96*104) * 4;         // 222,208 B
    const int TP_SMEM  = (128*100 + 96*104) * 4;           //  91,136 B
    const int FUS_SMEM = (2*128*100 + 192*104) * 4;        // 182,272 B
    const int ATS_SMEM = (2*64*97) * 4;                    //  49,664 B

    static cudaStream_t stB = 0, stC = 0;
    static cudaEvent_t evFork = 0, evB = 0, evC = 0;
    static int inited = 0;
    static int use_streams = 0;
    if (!inited) {
        cudaFuncSetAttribute(gemm_tc_sp, cudaFuncAttributeMaxDynamicSharedMemorySize, SP_SMEM);
        cudaFuncSetAttribute(gemm_tc_tp, cudaFuncAttributeMaxDynamicSharedMemorySize, TP_SMEM);
        cudaFuncSetAttribute(fusion_tc,  cudaFuncAttributeMaxDynamicSharedMemorySize, FUS_SMEM);
        cudaFuncSetAttribute(attnS_gemm, cudaFuncAttributeMaxDynamicSharedMemorySize, ATS_SMEM);
        use_streams = 1;
        if (cudaStreamCreateWithFlags(&stB, cudaStreamNonBlocking) != cudaSuccess) use_streams = 0;
        if (use_streams && cudaStreamCreateWithFlags(&stC, cudaStreamNonBlocking) != cudaSuccess) use_streams = 0;
        if (use_streams && cudaEventCreateWithFlags(&evFork, cudaEventDisableTiming) != cudaSuccess) use_streams = 0;
        if (use_streams && cudaEventCreateWithFlags(&evB,    cudaEventDisableTiming) != cudaSuccess) use_streams = 0;
        if (use_streams && cudaEventCreateWithFlags(&evC,    cudaEventDisableTiming) != cudaSuccess) use_streams = 0;
        inited = 1;
    }

    if (use_streams) {
        cudaStreamCaptureMode mode = cudaStreamCaptureModeRelaxed;
        cudaThreadExchangeStreamCaptureMode(&mode);

        cudaEventRecord(evFork, 0);
        cudaStreamWaitEvent(stB, evFork, 0);
        cudaStreamWaitEvent(stC, evFork, 0);

        // chain A first (critical path): spatial GEMM (3 gats) -> aggregation
        gemm_tc_sp<<<SPGRID, 512, SP_SMEM>>>(input, spatE,
            W_d, W_m, W_s, al_d, al_m, al_s, ar_d, ar_m, ar_s);
        gat_agg3<<<dim3(NN, 3), 256>>>(s0, s1, s2, b_d, b_m, b_s, input);

        // chain B: attn_T first (no deps), then projection, then temporal branch
        attnT_kernel<<<4, dim3(24,24), 0, stB>>>(tempE);
        gemm_tc_tp<<<RGRID, 256, TP_SMEM, stB>>>(input, Wg, agl, agr);
        temporal2<<<4096, 288, 0, stB>>>(input);
        cudaEventRecord(evB, stB);

        // chain C: attn_S output (independent)
        attnS_gemm<<<dim3(16,16,4), 256, ATS_SMEM, stC>>>(spatE, attnS);
        rowsoftmax1024<<<4096, 256, 0, stC>>>(attnS);
        cudaEventRecord(evC, stC);

        cudaStreamWaitEvent(0, evB, 0);
        fusion_tc<<<RGRID, 256, FUS_SMEM>>>(input, Wf, bf, out);
        cudaStreamWaitEvent(0, evC, 0);

        cudaThreadExchangeStreamCaptureMode(&mode);   // restore
    } else {
        // sequential fallback
        gemm_tc_sp<<<SPGRID, 512, SP_SMEM>>>(input, spatE,
            W_d, W_m, W_s, al_d, al_m, al_s, ar_d, ar_m, ar_s);
        gemm_tc_tp<<<RGRID, 256, TP_SMEM>>>(input, Wg, agl, agr);
        gat_agg3<<<dim3(NN, 3), 256>>>(s0, s1, s2, b_d, b_m, b_s, input);
        attnS_gemm<<<dim3(16,16,4), 256, ATS_SMEM>>>(spatE, attnS);
        rowsoftmax1024<<<4096, 256>>>(attnS);
        attnT_kernel<<<4, dim3(24,24)>>>(tempE);
        temporal2<<<4096, 288>>>(input);
        fusion_tc<<<RGRID, 256, FUS_SMEM>>>(input, Wf, bf, out);
    }
}

// round 16
// speedup vs baseline: 1.2652x; 1.0793x over previous
#include <cuda_runtime.h>
#include <cuda_fp16.h>
#include <math.h>
#include <stdint.h>

#define NN 1024
#define BB 4
#define TT 24
#define FF 96
#define RR (NN*96)       // 98304 rows (== B*T*N)
#define RGRID (RR/128)   // 768
#define SPGRID (RR/256)  // 384

// ---------------- scratch (device globals; no allocs allowed) ----------------
__device__ __half g_h3[3*(size_t)RR*96];  // spatial GAT h (fp16), per gat
__device__ float g_el3[3*RR*3];
__device__ float g_er3[3*RR*3];
__device__ float g_hg[(size_t)RR*96];     // temporal hg (fp32), row = (b*N+n)*24+t
__device__ float g_elg[RR*4];
__device__ float g_erg[RR*4];
__device__ float g_spatial[(size_t)RR*96];
__device__ float g_temporal[(size_t)RR*96];
__device__ float g_attnT[BB*TT*TT];

// ---------------- tf32 helpers ----------------
__device__ __forceinline__ uint32_t f2tf32(float x) {
    uint32_t r; asm("cvt.rna.tf32.f32 %0, %1;" : "=r"(r) : "f"(x)); return r;
}
__device__ __forceinline__ void mma_tf32(float* c, const uint32_t* a, uint32_t b0, uint32_t b1) {
    asm volatile("mma.sync.aligned.m16n8k8.row.col.f32.tf32.tf32.f32 "
        "{%0,%1,%2,%3}, {%4,%5,%6,%7}, {%8,%9}, {%0,%1,%2,%3};"
        : "+f"(c[0]), "+f"(c[1]), "+f"(c[2]), "+f"(c[3])
        : "r"(a[0]), "r"(a[1]), "r"(a[2]), "r"(a[3]), "r"(b0), "r"(b1));
}

// ======= spatial GEMM: 256 rows x 96 cols, 512 threads, ALL 3 GATs ===========
__global__ __launch_bounds__(512)
void gemm_tc_sp(const float* __restrict__ X, const float* __restrict__ Emb,
                const float* __restrict__ W0, const float* __restrict__ W1, const float* __restrict__ W2,
                const float* __restrict__ al0, const float* __restrict__ al1, const float* __restrict__ al2,
                const float* __restrict__ ar0, const float* __restrict__ ar1, const float* __restrict__ ar2)
{
    extern __shared__ float sm[];
    float*    Xs = sm;                                 // [256][100] fp32
    uint32_t* Ws = (uint32_t*)(sm + 256*100);          // 3 x [96][104] tf32

    const int tid = threadIdx.x;                       // 512
    const int row0 = blockIdx.x * 256;
    const float* Wp[3]  = {W0, W1, W2};
    const float* alp[3] = {al0, al1, al2};
    const float* arp[3] = {ar0, ar1, ar2};

    for (int i = tid; i < 3*2304; i += 512) {
        int gat = i / 2304, rem = i % 2304;
        int k = rem / 24, c4 = rem % 24;
        float4 v = reinterpret_cast<const float4*>(Wp[gat])[rem];
        *reinterpret_cast<uint4*>(&Ws[gat*96*104 + k*104 + c4*4]) =
            make_uint4(f2tf32(v.x), f2tf32(v.y), f2tf32(v.z), f2tf32(v.w));
    }
    for (int i = tid; i < 6144; i += 512) {
        int r = i / 24, c4 = i % 24;
        int gr = row0 + r;
        int n = gr / 96, k = gr % 96;
        int b = k & 3, t = k >> 2;
        int off = ((b*TT + t)*NN + n)*FF;
        float4 v = *reinterpret_cast<const float4*>(X + off + c4*4);
        float4 e = *reinterpret_cast<const float4*>(Emb + off + c4*4);
        v.x += e.x; v.y += e.y; v.z += e.z; v.w += e.w;
        *reinterpret_cast<float4*>(&Xs[r*100 + c4*4]) = v;
    }
    __syncthreads();

    const int lane = tid & 31, w = tid >> 5;           // w 0..15
    const int g = lane >> 2, tig = lane & 3;
    const int r0 = w * 16;
    const int gr0 = row0 + r0 + g, gr1 = gr0 + 8;

    uint32_t af[12][4];
    #pragma unroll
    for (int ks = 0; ks < 12; ++ks) {
        int k0 = ks * 8;
        af[ks][0] = f2tf32(Xs[(r0+g  )*100 + k0 + tig    ]);
        af[ks][1] = f2tf32(Xs[(r0+g+8)*100 + k0 + tig    ]);
        af[ks][2] = f2tf32(Xs[(r0+g  )*100 + k0 + tig + 4]);
        af[ks][3] = f2tf32(Xs[(r0+g+8)*100 + k0 + tig + 4]);
    }

    for (int gat = 0; gat < 3; ++gat) {
        const uint32_t* Wg_ = Ws + gat*96*104;
        float acc[12][4];
        #pragma unroll
        for (int nt = 0; nt < 12; ++nt)
            #pragma unroll
            for (int q = 0; q < 4; ++q) acc[nt][q] = 0.f;
        #pragma unroll
        for (int ks = 0; ks < 12; ++ks) {
            int k0 = ks * 8;
            #pragma unroll
            for (int nt = 0; nt < 12; ++nt) {
                uint32_t b0 = Wg_[(k0+tig  )*104 + nt*8 + g];
                uint32_t b1 = Wg_[(k0+tig+4)*104 + nt*8 + g];
                mma_tf32(acc[nt], af[ks], b0, b1);
            }
        }
        __half* Hb = g_h3 + (size_t)gat*RR*96;
        #pragma unroll
        for (int nt = 0; nt < 12; ++nt) {
            *reinterpret_cast<__half2*>(Hb + (size_t)gr0*96 + nt*8 + 2*tig) =
                __floats2half2_rn(acc[nt][0], acc[nt][1]);
            *reinterpret_cast<__half2*>(Hb + (size_t)gr1*96 + nt*8 + 2*tig) =
                __floats2half2_rn(acc[nt][2], acc[nt][3]);
        }
        const float* al = alp[gat];
        const float* ar = arp[gat];
        #pragma unroll
        for (int h = 0; h < 3; ++h) {
            float sl0 = 0.f, sr0 = 0.f, sl1 = 0.f, sr1 = 0.f;
            #pragma unroll
            for (int q = 0; q < 4; ++q) {
                int nt = h*4 + q;
                float a0 = al[nt*8 + 2*tig], a1 = al[nt*8 + 2*tig + 1];
                float c0 = ar[nt*8 + 2*tig], c1 = ar[nt*8 + 2*tig + 1];
                sl0 += acc[nt][0]*a0 + acc[nt][1]*a1;
                sr0 += acc[nt][0]*c0 + acc[nt][1]*c1;
                sl1 += acc[nt][2]*a0 + acc[nt][3]*a1;
                sr1 += acc[nt][2]*c0 + acc[nt][3]*c1;
            }
            sl0 += __shfl_xor_sync(0xffffffffu, sl0, 1); sl0 += __shfl_xor_sync(0xffffffffu, sl0, 2);
            sr0 += __shfl_xor_sync(0xffffffffu, sr0, 1); sr0 += __shfl_xor_sync(0xffffffffu, sr0, 2);
            sl1 += __shfl_xor_sync(0xffffffffu, sl1, 1); sl1 += __shfl_xor_sync(0xffffffffu, sl1, 2);
            sr1 += __shfl_xor_sync(0xffffffffu, sr1, 1); sr1 += __shfl_xor_sync(0xffffffffu, sr1, 2);
            if (tig == 0) {
                g_el3[(size_t)gat*RR*3 + gr0*3 + h] = sl0;
                g_er3[(size_t)gat*RR*3 + gr0*3 + h] = sr0;
                g_el3[(size_t)gat*RR*3 + gr1*3 + h] = sl1;
                g_er3[(size_t)gat*RR*3 + gr1*3 + h] = sr1;
            }
        }
    }
}

// ======= temporal projection GEMM v3: no X staging, 24-warp occupancy ========
// A-fragments read straight from global (BTN-linear rows; L1-resident after
// first touch). Static 39KB smem (W only) + reg cap -> 3 CTAs/SM.
__global__ __launch_bounds__(256, 3)
void gemm_tc_tp(const float* __restrict__ X, const float* __restrict__ W,
                const float* __restrict__ al, const float* __restrict__ ar)
{
    __shared__ uint32_t Ws[96*104];                    // 39,936 B
    const int tid = threadIdx.x;
    const int row0 = blockIdx.x * 128;                 // input-linear row base

    for (int i = tid; i < 2304; i += 256) {
        int k = i / 24, c4 = i % 24;
        float4 v = reinterpret_cast<const float4*>(W)[i];
        *reinterpret_cast<uint4*>(&Ws[k*104 + c4*4]) =
            make_uint4(f2tf32(v.x), f2tf32(v.y), f2tf32(v.z), f2tf32(v.w));
    }
    __syncthreads();

    const int lane = tid & 31, w = tid >> 5;
    const int g = lane >> 2, tig = lane & 3;
    const int r0 = w * 16;
    const float* Xb = X + (size_t)row0 * 96;
    float acc[12][4];
    #pragma unroll
    for (int nt = 0; nt < 12; ++nt)
        #pragma unroll
        for (int q = 0; q < 4; ++q) acc[nt][q] = 0.f;
    #pragma unroll
    for (int ks = 0; ks < 12; ++ks) {
        int k0 = ks * 8;
        uint32_t a[4];
        a[0] = f2tf32(Xb[(r0+g  )*96 + k0 + tig    ]);
        a[1] = f2tf32(Xb[(r0+g+8)*96 + k0 + tig    ]);
        a[2] = f2tf32(Xb[(r0+g  )*96 + k0 + tig + 4]);
        a[3] = f2tf32(Xb[(r0+g+8)*96 + k0 + tig + 4]);
        #pragma unroll
        for (int nt = 0; nt < 12; ++nt) {
            uint32_t b0 = Ws[(k0+tig  )*104 + nt*8 + g];
            uint32_t b1 = Ws[(k0+tig+4)*104 + nt*8 + g];
            mma_tf32(acc[nt], a, b0, b1);
        }
    }
    // map input-linear rows -> (b*N+n)*24+t output rows
    const int ir0 = row0 + r0 + g, ir1 = ir0 + 8;
    const int n0 = ir0 & 1023, bt0 = ir0 >> 10;
    const int n1 = ir1 & 1023, bt1 = ir1 >> 10;
    const int b0r = bt0 / 24, t0r = bt0 % 24;
    const int b1r = bt1 / 24, t1r = bt1 % 24;
    const int ro0 = ((b0r*NN + n0)*TT + t0r);
    const int ro1 = ((b1r*NN + n1)*TT + t1r);
    #pragma unroll
    for (int nt = 0; nt < 12; ++nt) {
        *reinterpret_cast<float2*>(g_hg + (size_t)ro0*96 + nt*8 + 2*tig) = make_float2(acc[nt][0], acc[nt][1]);
        *reinterpret_cast<float2*>(g_hg + (size_t)ro1*96 + nt*8 + 2*tig) = make_float2(acc[nt][2], acc[nt][3]);
    }
    #pragma unroll
    for (int h = 0; h < 4; ++h) {
        float sl0 = 0.f, sr0 = 0.f, sl1 = 0.f, sr1 = 0.f;
        #pragma unroll
        for (int q = 0; q < 3; ++q) {
            int nt = h*3 + q;
            float a0 = al[nt*8 + 2*tig], a1 = al[nt*8 + 2*tig + 1];
            float c0 = ar[nt*8 + 2*tig], c1 = ar[nt*8 + 2*tig + 1];
            sl0 += acc[nt][0]*a0 + acc[nt][1]*a1;
            sr0 += acc[nt][0]*c0 + acc[nt][1]*c1;
            sl1 += acc[nt][2]*a0 + acc[nt][3]*a1;
            sr1 += acc[nt][2]*c0 + acc[nt][3]*c1;
        }
        sl0 += __shfl_xor_sync(0xffffffffu, sl0, 1); sl0 += __shfl_xor_sync(0xffffffffu, sl0, 2);
        sr0 += __shfl_xor_sync(0xffffffffu, sr0, 1); sr0 += __shfl_xor_sync(0xffffffffu, sr0, 2);
        sl1 += __shfl_xor_sync(0xffffffffu, sl1, 1); sl1 += __shfl_xor_sync(0xffffffffu, sl1, 2);
        sr1 += __shfl_xor_sync(0xffffffffu, sr1, 1); sr1 += __shfl_xor_sync(0xffffffffu, sr1, 2);
        if (tig == 0) {
            g_elg[ro0*4 + h] = sl0;  g_erg[ro0*4 + h] = sr0;
            g_elg[ro1*4 + h] = sl1;  g_erg[ro1*4 + h] = sr1;
        }
    }
}

// -------- GAT aggregation v3: half2 gather, thread = (dd 0..15, kg 0..15) ----
__global__ __launch_bounds__(256)
void gat_agg3(const int* __restrict__ src0, const int* __restrict__ src1,
              const int* __restrict__ src2,
              const float* __restrict__ bias0, const float* __restrict__ bias1,
              const float* __restrict__ bias2,
              const float* __restrict__ inp)
{
    const int gat = blockIdx.y, n = blockIdx.x, tid = threadIdx.x;
    const int*   src  = (gat == 0) ? src0  : (gat == 1) ? src1  : src2;
    const float* bias = (gat == 0) ? bias0 : (gat == 1) ? bias1 : bias2;
    const __half* H  = g_h3  + (size_t)gat*RR*96;
    const float* EL = g_el3 + (size_t)gat*RR*3;
    const float* ER = g_er3 + (size_t)gat*RR*3;

    __shared__ int   ssm[8];
    __shared__ float er_s[288];
    __shared__ float as[2304];      // [q = k*3+h][j]
    __shared__ float bsum[32];

    if (tid < 8)  ssm[tid] = src[n + tid*NN];
    if (tid < 32) bsum[tid] = bias[tid] + bias[32 + tid] + bias[64 + tid];
    for (int q = tid; q < 288; q += 256) er_s[q] = ER[n*288 + q];
    __syncthreads();

    for (int j = 0; j < 8; ++j) {
        const float* elp = EL + (size_t)ssm[j] * 288;
        for (int q = tid; q < 288; q += 256) {
            float x = elp[q] + er_s[q];
            as[q*8 + j] = (x >= 0.f) ? x : 0.2f*x;
        }
    }
    __syncthreads();
    for (int q = tid; q < 288; q += 256) {
        float e[8], m = -1e30f;
        #pragma unroll
        for (int j = 0; j < 8; ++j) { e[j] = as[q*8 + j]; m = fmaxf(m, e[j]); }
        float s = 0.f;
        #pragma unroll
        for (int j = 0; j < 8; ++j) { e[j] = expf(e[j] - m); s += e[j]; }
        float inv = 1.f / (s + 1e-9f);
        #pragma unroll
        for (int j = 0; j < 8; ++j) as[q*8 + j] = e[j] * inv;
    }
    __syncthreads();

    const int dd = tid & 15, kg = tid >> 4;
    float2 acc[6];
    #pragma unroll
    for (int s = 0; s < 6; ++s) acc[s] = make_float2(0.f, 0.f);
    for (int j = 0; j < 8; ++j) {
        const __half2* hb2 = reinterpret_cast<const __half2*>(H + (size_t)ssm[j] * 96 * 96);
        #pragma unroll
        for (int s = 0; s < 6; ++s) {
            int k = kg + 16*s;
            const __half2* hp2 = hb2 + k*48;
            float a0 = as[(k*3+0)*8 + j];
            float a1 = as[(k*3+1)*8 + j];
            float a2 = as[(k*3+2)*8 + j];
            float2 h0 = __half22float2(hp2[dd]);
            float2 h1 = __half22float2(hp2[16 + dd]);
            float2 h2 = __half22float2(hp2[32 + dd]);
            acc[s].x += a0*h0.x + a1*h1.x + a2*h2.x;
            acc[s].y += a0*h0.y + a1*h1.y + a2*h2.y;
        }
    }
    float b0v = bsum[2*dd], b1v = bsum[2*dd + 1];
    #pragma unroll
    for (int s = 0; s < 6; ++s) {
        int k = kg + 16*s;
        float vx = (acc[s].x + b0v) * (1.f/3.f);
        float vy = (acc[s].y + b1v) * (1.f/3.f);
        int ob = k / 24, ot = k % 24;      // reference's reshape scramble
        size_t o = (size_t)((ob*TT + ot)*NN + n)*FF + gat*32 + 2*dd;
        float2 iv = *reinterpret_cast<const float2*>(inp + o);
        *reinterpret_cast<float2*>(g_spatial + o) = make_float2(iv.x + vx, iv.y + vy);
    }
}

// ---------------- attn_S = softmax(cov0 @ cov0^T, axis=2) -- fp32 ------------
__global__ __launch_bounds__(256)
void attnS_gemm(const float* __restrict__ spatE, float* __restrict__ Sout)
{
    extern __shared__ float sm2[];
    float* At = sm2;            // [64][97]
    float* Bt = sm2 + 64*97;    // [64][97]
    int b = blockIdx.z;
    int i0 = blockIdx.y * 64, j0 = blockIdx.x * 64;
    const float* cov = spatE + (size_t)b*TT*NN*FF;   // t = 0 slice
    int tid = threadIdx.x;       // 256
    #pragma unroll
    for (int i = 0; i < 6; ++i) {
        int idx = tid + i*256;   // < 1536
        int r = idx / 24, c4 = idx % 24;
        float4 v = *reinterpret_cast<const float4*>(cov + (i0 + r)*96 + c4*4);
        At[r*97 + c4*4+0] = v.x; At[r*97 + c4*4+1] = v.y;
        At[r*97 + c4*4+2] = v.z; At[r*97 + c4*4+3] = v.w;
        float4 w = *reinterpret_cast<const float4*>(cov + (j0 + r)*96 + c4*4);
        Bt[r*97 + c4*4+0] = w.x; Bt[r*97 + c4*4+1] = w.y;
        Bt[r*97 + c4*4+2] = w.z; Bt[r*97 + c4*4+3] = w.w;
    }
    __syncthreads();
    int tx = tid & 15, ty = tid >> 4;
    float acc[4][4];
    #pragma unroll
    for (int u = 0; u < 4; ++u)
        #pragma unroll
        for (int v = 0; v < 4; ++v) acc[u][v] = 0.f;
    #pragma unroll 8
    for (int f = 0; f < 96; ++f) {
        float a[4], bb[4];
        #pragma unroll
        for (int u = 0; u < 4; ++u) a[u] = At[(ty*4+u)*97 + f];
        #pragma unroll
        for (int v = 0; v < 4; ++v) bb[v] = Bt[(tx*4+v)*97 + f];
        #pragma unroll
        for (int u = 0; u < 4; ++u)
            #pragma unroll
            for (int v = 0; v < 4; ++v) acc[u][v] = fmaf(a[u], bb[v], acc[u][v]);
    }
    #pragma unroll
    for (int u = 0; u < 4; ++u) {
        float4 o = make_float4(acc[u][0], acc[u][1], acc[u][2], acc[u][3]);
        *reinterpret_cast<float4*>(Sout + ((size_t)b*NN + i0 + ty*4 + u)*NN + j0 + tx*4) = o;
    }
}

__global__ void rowsoftmax1024(float* __restrict__ S)
{
    int row = blockIdx.x;
    float* p = S + (size_t)row * 1024;
    int tid = threadIdx.x;   // 256
    float v[4];
    float m = -1e30f;
    #pragma unroll
    for (int q = 0; q < 4; ++q) { v[q] = p[tid + q*256]; m = fmaxf(m, v[q]); }
    __shared__ float red[8];
    __shared__ float red2[8];
    for (int o = 16; o >= 1; o >>= 1) m = fmaxf(m, __shfl_xor_sync(0xffffffffu, m, o));
    if ((tid & 31) == 0) red[tid >> 5] = m;
    __syncthreads();
    float mm = red[0];
    #pragma unroll
    for (int w = 1; w < 8; ++w) mm = fmaxf(mm, red[w]);
    float s = 0.f;
    #pragma unroll
    for (int q = 0; q < 4; ++q) { v[q] = expf(v[q] - mm); s += v[q]; }
    for (int o = 16; o >= 1; o >>= 1) s += __shfl_xor_sync(0xffffffffu, s, o);
    if ((tid & 31) == 0) red2[tid >> 5] = s;
    __syncthreads();
    float ss = 0.f;
    #pragma unroll
    for (int w = 0; w < 8; ++w) ss += red2[w];
    float inv = 1.f / ss;
    #pragma unroll
    for (int q = 0; q < 4; ++q) p[tid + q*256] = v[q] * inv;
}

// ---------------- attn_T = softmax(covT @ covT^T, axis=1) --------------------
__global__ void attnT_kernel(const float* __restrict__ tempE)
{
    __shared__ float cov[24][96];
    __shared__ float s[24][25];
    __shared__ float colmax[24], colsum[24];
    int b = blockIdx.x;
    int j = threadIdx.x, i = threadIdx.y;
    int tid = i*24 + j;
    for (int q = tid; q < 2304; q += 576) {
        int t = q / 96, f = q % 96;
        cov[t][f] = tempE[((b*TT + t)*NN)*FF + f];   // n = 0 slice
    }
    __syncthreads();
    float acc = 0.f;
    #pragma unroll
    for (int f = 0; f < 96; ++f) acc = fmaf(cov[i][f], cov[j][f], acc);
    s[i][j] = acc;
    __syncthreads();
    if (i == 0) {
        float m = -1e30f;
        for (int t = 0; t < 24; ++t) m = fmaxf(m, s[t][j]);
        colmax[j] = m;
    }
    __syncthreads();
    float e = expf(acc - colmax[j]);
    s[i][j] = e;
    __syncthreads();
    if (i == 0) {
        float sm0 = 0.f;
        for (int t = 0; t < 24; ++t) sm0 += s[t][j];
        colsum[j] = sm0;
    }
    __syncthreads();
    g_attnT[(b*TT + i)*TT + j] = e / colsum[j];
}

// ---------------- temporal branch v2: 288 threads, register-hoisted ----------
__global__ __launch_bounds__(288)
void temporal2(const float* __restrict__ input)
{
    __shared__ float hgs[2304];
    __shared__ float xts[2304];
    __shared__ float alph[2304];
    __shared__ float ats[576];
    __shared__ float elgs[96], ergs[96];
    int r = blockIdx.x;              // r = b*N + n
    int b = r >> 10, n = r & 1023;
    int tid = threadIdx.x;           // 288
    for (int q = tid; q < 2304; q += 288) hgs[q] = g_hg[(size_t)r*2304 + q];
    for (int q = tid; q < 2304; q += 288) {
        int t = q / 96, f = q % 96;
        xts[q] = input[((b*TT + t)*NN + n)*FF + f];
    }
    if (tid < 96) { elgs[tid] = g_elg[r*96 + tid]; ergs[tid] = g_erg[r*96 + tid]; }
    for (int q = tid; q < 576; q += 288) ats[q] = g_attnT[(n & 3)*576 + q]; // idx = r%B = n%4
    __syncthreads();
    if (tid < 96) {                  // softmax over j for (i,g)
        int i = tid >> 2, g = tid & 3;
        float eli = elgs[i*4 + g];
        float ev[24];
        float m = -1e30f;
        #pragma unroll
        for (int j = 0; j < 24; ++j) {
            float x = eli + ergs[j*4 + g];
            x = (x >= 0.f) ? x : 0.2f*x;
            ev[j] = x;
            m = fmaxf(m, x);
        }
        float s = 0.f;
        #pragma unroll
        for (int j = 0; j < 24; ++j) { ev[j] = expf(ev[j] - m); s += ev[j]; }
        float inv = 1.f / s;
        #pragma unroll
        for (int j = 0; j < 24; ++j) alph[tid*24 + j] = ev[j]*inv;
    }
    __syncthreads();

    int f = tid % 96, tr = tid / 96;       // tr 0..2
    int g = f / 24;
    float hv[24], xv[24];
    #pragma unroll
    for (int j = 0; j < 24; ++j) { hv[j] = hgs[j*96 + f]; xv[j] = xts[j*96 + f]; }
    #pragma unroll
    for (int s = 0; s < 8; ++s) {
        int i = tr + 3*s;
        float xa = 0.f, ea = 0.f;
        const float* ap = &alph[(i*4 + g)*24];
        const float* tp = &ats[i*24];
        #pragma unroll
        for (int j = 0; j < 24; ++j) {
            xa = fmaf(ap[j], hv[j], xa);
            ea = fmaf(tp[j], xv[j], ea);
        }
        float sg = 1.f / (1.f + expf(-ea));
        g_temporal[(size_t)((b*TT + i)*NN + n)*FF + f] = xv[i] + xa*sg;
    }
}

// ---- fusion v2: split-k across 16 warps (512 threads); halves combined via
// the Ws smem region (re-used after MMA; 49,152 B partials < 79,872 B Ws). ----
__global__ __launch_bounds__(512)
void fusion_tc(const float* __restrict__ input, const float* __restrict__ Wf,
               const float* __restrict__ bf, float* __restrict__ outp)
{
    extern __shared__ float sm[];
    float*    Xsp = sm;                                  // [128][100] fp32
    float*    Xtp = sm + 128*100;                        // [128][100] fp32
    uint32_t* Ws  = (uint32_t*)(sm + 2*128*100);         // [192][104] tf32
    float*    Prt = (float*)Ws;                          // partials overlay

    const int tid = threadIdx.x;                         // 512
    const int row0 = blockIdx.x * 128;

    for (int i = tid; i < 192*24; i += 512) {
        int k = i / 24, c4 = i % 24;
        float4 v = reinterpret_cast<const float4*>(Wf)[i];
        *reinterpret_cast<uint4*>(&Ws[k*104 + c4*4]) =
            make_uint4(f2tf32(v.x), f2tf32(v.y), f2tf32(v.z), f2tf32(v.w));
    }
    for (int i = tid; i < 3072; i += 512) {
        int r = i / 24, c4 = i % 24;
        size_t off = (size_t)(row0 + r)*96 + c4*4;
        *reinterpret_cast<float4*>(&Xsp[r*100 + c4*4]) = *reinterpret_cast<const float4*>(g_spatial + off);
        *reinterpret_cast<float4*>(&Xtp[r*100 + c4*4]) = *reinterpret_cast<const float4*>(g_temporal + off);
    }
    __syncthreads();

    const int lane = tid & 31, w = tid >> 5;
    const int half = w >> 3, wl = w & 7;                 // half 0: spatial, 1: temporal
    const int g = lane >> 2, tig = lane & 3;
    const int r0 = wl * 16;

    float acc[12][4];
    #pragma unroll
    for (int nt = 0; nt < 12; ++nt)
        #pragma unroll
        for (int q = 0; q < 4; ++q) acc[nt][q] = 0.f;

    const float*    Xh = (half == 0) ? Xsp : Xtp;
    const uint32_t* Wh = Ws + (half == 0 ? 0 : 96*104);
    #pragma unroll
    for (int ks = 0; ks < 12; ++ks) {
        int k0 = ks * 8;
        uint32_t a[4];
        a[0] = f2tf32(Xh[(r0+g  )*100 + k0 + tig    ]);
        a[1] = f2tf32(Xh[(r0+g+8)*100 + k0 + tig    ]);
        a[2] = f2tf32(Xh[(r0+g  )*100 + k0 + tig + 4]);
        a[3] = f2tf32(Xh[(r0+g+8)*100 + k0 + tig + 4]);
        #pragma unroll
        for (int nt = 0; nt < 12; ++nt) {
            uint32_t b0 = Wh[(k0+tig  )*104 + nt*8 + g];
            uint32_t b1 = Wh[(k0+tig+4)*104 + nt*8 + g];
            mma_tf32(acc[nt], a, b0, b1);
        }
    }

    __syncthreads();                 // all MMAs done before Ws is overwritten
    if (half == 1) {                 // temporal-half warps publish partials
        float* p = Prt + ((size_t)wl*32 + lane)*48;
        #pragma unroll
        for (int nt = 0; nt < 12; ++nt) {
            p[nt*4+0] = acc[nt][0]; p[nt*4+1] = acc[nt][1];
            p[nt*4+2] = acc[nt][2]; p[nt*4+3] = acc[nt][3];
        }
    }
    __syncthreads();
    if (half == 0) {                 // spatial-half warps combine + epilogue
        const float* p = Prt + ((size_t)wl*32 + lane)*48;
        #pragma unroll
        for (int nt = 0; nt < 12; ++nt) {
            acc[nt][0] += p[nt*4+0]; acc[nt][1] += p[nt*4+1];
            acc[nt][2] += p[nt*4+2]; acc[nt][3] += p[nt*4+3];
        }
        const int gr0 = row0 + r0 + g, gr1 = gr0 + 8;
        const int rl0 = r0 + g, rl1 = rl0 + 8;
        #pragma unroll
        for (int nt = 0; nt < 12; ++nt) {
            int col = nt*8 + 2*tig;
            float b0v = bf[col], b1v = bf[col+1];
            float2 in0 = *reinterpret_cast<const float2*>(input + (size_t)gr0*96 + col);
            float2 in1 = *reinterpret_cast<const float2*>(input + (size_t)gr1*96 + col);
            float z00 = 1.f/(1.f+expf(-(acc[nt][0] + b0v)));
            float z01 = 1.f/(1.f+expf(-(acc[nt][1] + b1v)));
            float z10 = 1.f/(1.f+expf(-(acc[nt][2] + b0v)));
            float z11 = 1.f/(1.f+expf(-(acc[nt][3] + b1v)));
            float sp00 = Xsp[rl0*100 + col], sp01 = Xsp[rl0*100 + col + 1];
            float sp10 = Xsp[rl1*100 + col], sp11 = Xsp[rl1*100 + col + 1];
            float tp00 = Xtp[rl0*100 + col], tp01 = Xtp[rl0*100 + col + 1];
            float tp10 = Xtp[rl1*100 + col], tp11 = Xtp[rl1*100 + col + 1];
            float2 o0 = make_float2(z00*sp00 + (1.f-z00)*tp00 + in0.x,
                                    z01*sp01 + (1.f-z01)*tp01 + in0.y);
            float2 o1 = make_float2(z10*sp10 + (1.f-z10)*tp10 + in1.x,
                                    z11*sp11 + (1.f-z11)*tp11 + in1.y);
            *reinterpret_cast<float2*>(outp + (size_t)gr0*96 + col) = o0;
            *reinterpret_cast<float2*>(outp + (size_t)gr1*96 + col) = o1;
        }
    }
}

extern "C" void kernel_launch(void* const* d_in, const int* in_sizes, int n_in,
                              void* d_out, int out_size)
{
    const float* input = (const float*)d_in[0];
    const float* spatE = (const float*)d_in[1];
    const float* tempE = (const float*)d_in[2];
    const int*   s0 = (const int*)d_in[3];
    const int*   s1 = (const int*)d_in[5];
    const int*   s2 = (const int*)d_in[7];
    const float* W_d = (const float*)d_in[9];
    const float* al_d = (const float*)d_in[10];
    const float* ar_d = (const float*)d_in[11];
    const float* b_d = (const float*)d_in[12];
    const float* W_m = (const float*)d_in[13];
    const float* al_m = (const float*)d_in[14];
    const float* ar_m = (const float*)d_in[15];
    const float* b_m = (const float*)d_in[16];
    const float* W_s = (const float*)d_in[17];
    const float* al_s = (const float*)d_in[18];
    const float* ar_s = (const float*)d_in[19];
    const float* b_s = (const float*)d_in[20];
    const float* Wg  = (const float*)d_in[21];
    const float* agl = (const float*)d_in[22];
    const float* agr = (const float*)d_in[23];
    const float* Wf  = (const float*)d_in[24];
    const float* bf  = (const float*)d_in[25];
    float* out   = (float*)d_out;
    float* attnS = out + (size_t)RR*96;   // out (B,T,N,F) then attn_S (B,N,N)

    const int SP_SMEM  = (256*100 + 3*96*104) * 4;         // 222,208 B
    const int FUS_SMEM = (2*128*100 + 192*104) * 4;        // 182,272 B
    const int ATS_SMEM = (2*64*97) * 4;                    //  49,664 B

    static cudaStream_t stB = 0, stC = 0;
    static cudaEvent_t evFork = 0, evB = 0, evC = 0;
    static int inited = 0;
    static int use_streams = 0;
    if (!inited) {
        cudaFuncSetAttribute(gemm_tc_sp, cudaFuncAttributeMaxDynamicSharedMemorySize, SP_SMEM);
        cudaFuncSetAttribute(fusion_tc,  cudaFuncAttributeMaxDynamicSharedMemorySize, FUS_SMEM);
        cudaFuncSetAttribute(attnS_gemm, cudaFuncAttributeMaxDynamicSharedMemorySize, ATS_SMEM);
        use_streams = 1;
        if (cudaStreamCreateWithFlags(&stB, cudaStreamNonBlocking) != cudaSuccess) use_streams = 0;
        if (use_streams && cudaStreamCreateWithFlags(&stC, cudaStreamNonBlocking) != cudaSuccess) use_streams = 0;
        if (use_streams && cudaEventCreateWithFlags(&evFork, cudaEventDisableTiming) != cudaSuccess) use_streams = 0;
        if (use_streams && cudaEventCreateWithFlags(&evB,    cudaEventDisableTiming) != cudaSuccess) use_streams = 0;
        if (use_streams && cudaEventCreateWithFlags(&evC,    cudaEventDisableTiming) != cudaSuccess) use_streams = 0;
        inited = 1;
    }

    if (use_streams) {
        cudaStreamCaptureMode mode = cudaStreamCaptureModeRelaxed;
        cudaThreadExchangeStreamCaptureMode(&mode);

        cudaEventRecord(evFork, 0);
        cudaStreamWaitEvent(stB, evFork, 0);
        cudaStreamWaitEvent(stC, evFork, 0);

        // chain A first (critical path): spatial GEMM (3 gats) -> aggregation
        gemm_tc_sp<<<SPGRID, 512, SP_SMEM>>>(input, spatE,
            W_d, W_m, W_s, al_d, al_m, al_s, ar_d, ar_m, ar_s);
        gat_agg3<<<dim3(NN, 3), 256>>>(s0, s1, s2, b_d, b_m, b_s, input);

        // chain B: attn_T first (no deps), then projection, then temporal branch
        attnT_kernel<<<4, dim3(24,24), 0, stB>>>(tempE);
        gemm_tc_tp<<<RGRID, 256, 0, stB>>>(input, Wg, agl, agr);
        temporal2<<<4096, 288, 0, stB>>>(input);
        cudaEventRecord(evB, stB);

        // chain C: attn_S output (independent)
        attnS_gemm<<<dim3(16,16,4), 256, ATS_SMEM, stC>>>(spatE, attnS);
        rowsoftmax1024<<<4096, 256, 0, stC>>>(attnS);
        cudaEventRecord(evC, stC);

        cudaStreamWaitEvent(0, evB, 0);
        fusion_tc<<<RGRID, 512, FUS_SMEM>>>(input, Wf, bf, out);
        cudaStreamWaitEvent(0, evC, 0);

        cudaThreadExchangeStreamCaptureMode(&mode);   // restore
    } else {
        // sequential fallback
        gemm_tc_sp<<<SPGRID, 512, SP_SMEM>>>(input, spatE,
            W_d, W_m, W_s, al_d, al_m, al_s, ar_d, ar_m, ar_s);
        gemm_tc_tp<<<RGRID, 256>>>(input, Wg, agl, agr);
        gat_agg3<<<dim3(NN, 3), 256>>>(s0, s1, s2, b_d, b_m, b_s, input);
        attnS_gemm<<<dim3(16,16,4), 256, ATS_SMEM>>>(spatE, attnS);
        rowsoftmax1024<<<4096, 256>>>(attnS);
        attnT_kernel<<<4, dim3(24,24)>>>(tempE);
        temporal2<<<4096, 288>>>(input);
        fusion_tc<<<RGRID, 512, FUS_SMEM>>>(input, Wf, bf, out);
    }
}